// round 4
// baseline (speedup 1.0000x reference)
#include <cuda_runtime.h>
#include <math.h>

#define N_I 60000
#define N_E 30000
#define DI  128
#define DE  64
#define HH  64
#define E_II 960000
#define E_EI 480000
#define N_TRAIN 2048
#define N_CHOSEN 1024
#define F_INTERP 0.35f
#define F_SLOPE  0.2f
#define CAP_II 64
#define CAP_EI 48
#define TII ((N_I + 127) / 128)   // 469
#define TEI ((N_E + 127) / 128)   // 235
#define SB  64                    // scatter blocks in phase 1
#define SMEM_FLOATS (64*130 + 64*64 + 64 + 128)   // 12608
#define SMEM_BYTES  (SMEM_FLOATS * 4)             // 50432

// ---------------- scratch (static device globals; no allocation) ----------------
__device__ __align__(16) float g_hs_ii[N_I * HH];
__device__ __align__(16) float g_hs_ei[N_E * HH];
__device__ __align__(16) float g_emb[N_I * HH];
__device__ float g_s_ii[N_I];
__device__ float g_d_ii[N_I];
__device__ float g_d_ei[N_I];
__device__ float g_s_ei[N_E];
__device__ int   g_deg_ii[N_I];
__device__ int   g_deg_ei[N_I];
__device__ int   g_bkt_ii[(size_t)N_I * CAP_II];
__device__ int   g_bkt_ei[(size_t)N_I * CAP_EI];
__device__ __align__(16) float g_ce[N_CHOSEN * HH];
__device__ float g_sq[N_CHOSEN];
__device__ int   g_nb[N_CHOSEN];
__device__ float g_wd_ii[DI];
__device__ float g_wd_ei[DI];
__device__ int   g_trainflag[N_I];
__device__ int   g_invch[N_I];
__device__ unsigned g_cnt = 0;
__device__ unsigned g_gen = 0;

// ---------------- software grid barrier (all blocks resident) ----------------
__device__ __forceinline__ void gbar() {
    __syncthreads();
    if (threadIdx.x == 0) {
        volatile unsigned* vg = &g_gen;
        unsigned my = *vg;
        __threadfence();
        if (atomicAdd(&g_cnt, 1u) == gridDim.x - 1) {
            g_cnt = 0;
            __threadfence();
            *vg = my + 1;
        } else {
            while (*vg == my) __nanosleep(64);
        }
        __threadfence();
    }
    __syncthreads();
}

// ---------------- packed f32x2 helpers (Blackwell FFMA2) ----------------
__device__ __forceinline__ unsigned long long pk2(float x) {
    unsigned long long r;
    asm("mov.b64 %0, {%1, %1};" : "=l"(r) : "f"(x));
    return r;
}
__device__ __forceinline__ void fma2(unsigned long long& d, unsigned long long a,
                                     unsigned long long b) {
    asm("fma.rn.f32x2 %0, %1, %2, %0;" : "+l"(d) : "l"(a), "l"(b));
}
__device__ __forceinline__ void upk(unsigned long long v, float& lo, float& hi) {
    asm("mov.b64 {%0, %1}, %2;" : "=f"(lo), "=f"(hi) : "l"(v));
}

// ---------------- GEMM tile (256 threads): HS = A@W, S = HS@asrc, D = A@wd ----------------
// BM=128, BN=64, K chunked by 64. Thread (tr,tc): rows 4tr..4tr+3 x cols 8tc..8tc+7.
__device__ void gemm_tile(const float* __restrict__ A, const float* __restrict__ W,
                          const float* __restrict__ asrc,
                          const float* __restrict__ wd0, const float* __restrict__ wd1,
                          float* __restrict__ HS, float* __restrict__ S,
                          float* __restrict__ D0, float* __restrict__ D1,
                          int M, int K, int row0, float* sm) {
    float* As  = sm;              // [64][130]
    float* Ws  = sm + 64 * 130;   // [64][64]
    float* asc = Ws + 64 * 64;    // [64]
    float* wds = asc + 64;        // [128]

    const int tid  = threadIdx.x;
    const int Mloc = M - row0;
    const int tr = tid >> 3;      // 0..31
    const int tc = tid & 7;       // 0..7

    unsigned long long acc[2][8];
#pragma unroll
    for (int p = 0; p < 2; p++)
#pragma unroll
        for (int j = 0; j < 8; j++) acc[p][j] = 0ull;
    float d0 = 0.f, d1 = 0.f;

    const int nch = K >> 6;
    for (int ch = 0; ch < nch; ch++) {
        const int kk = ch << 6;
        __syncthreads();
        for (int i = tid; i < 128 * 64; i += 256) {
            int r = i >> 6, k = i & 63;
            As[k * 130 + r] = (r < Mloc) ? A[(size_t)(row0 + r) * K + kk + k] : 0.f;
        }
        for (int i = tid; i < 64 * 64; i += 256) Ws[i] = W[kk * 64 + i];
        if (ch == 0 && tid < 64) asc[tid] = asrc[tid];
        if (wd0 && tid < 64) { wds[tid] = wd0[kk + tid]; wds[64 + tid] = wd1[kk + tid]; }
        __syncthreads();

        const float* AsB = As + tr * 4;
        const float* WsB = Ws + tc * 8;
        for (int k = 0; k < 64; k++) {
            unsigned long long a0 = *(const unsigned long long*)(AsB + k * 130);
            unsigned long long a1 = *(const unsigned long long*)(AsB + k * 130 + 2);
            float4 b0 = *(const float4*)(WsB + k * 64);
            float4 b1 = *(const float4*)(WsB + k * 64 + 4);
            unsigned long long bd[8];
            bd[0] = pk2(b0.x); bd[1] = pk2(b0.y); bd[2] = pk2(b0.z); bd[3] = pk2(b0.w);
            bd[4] = pk2(b1.x); bd[5] = pk2(b1.y); bd[6] = pk2(b1.z); bd[7] = pk2(b1.w);
#pragma unroll
            for (int j = 0; j < 8; j++) {
                fma2(acc[0][j], a0, bd[j]);
                fma2(acc[1][j], a1, bd[j]);
            }
        }
        if (wd0 && tid < 128 && tid < Mloc) {
            for (int k = 0; k < 64; k++) {
                float a = As[k * 130 + tid];
                d0 += a * wds[k];
                d1 += a * wds[64 + k];
            }
        }
    }

    float ar[8];
#pragma unroll
    for (int j = 0; j < 8; j++) ar[j] = asc[tc * 8 + j];

#pragma unroll
    for (int p = 0; p < 2; p++) {
        float lo[8], hi[8];
#pragma unroll
        for (int j = 0; j < 8; j++) upk(acc[p][j], lo[j], hi[j]);
        int rl = tr * 4 + 2 * p;
        int rh = rl + 1;
        float sl = lo[0]*ar[0]+lo[1]*ar[1]+lo[2]*ar[2]+lo[3]*ar[3]+lo[4]*ar[4]+lo[5]*ar[5]+lo[6]*ar[6]+lo[7]*ar[7];
        float sh = hi[0]*ar[0]+hi[1]*ar[1]+hi[2]*ar[2]+hi[3]*ar[3]+hi[4]*ar[4]+hi[5]*ar[5]+hi[6]*ar[6]+hi[7]*ar[7];
#pragma unroll
        for (int off = 4; off; off >>= 1) {
            sl += __shfl_down_sync(0xffffffffu, sl, off, 8);
            sh += __shfl_down_sync(0xffffffffu, sh, off, 8);
        }
        if (rl < Mloc) {
            float* dl = &HS[(size_t)(row0 + rl) * 64 + tc * 8];
            *(float4*)dl       = make_float4(lo[0], lo[1], lo[2], lo[3]);
            *(float4*)(dl + 4) = make_float4(lo[4], lo[5], lo[6], lo[7]);
            if (tc == 0) S[row0 + rl] = sl;
        }
        if (rh < Mloc) {
            float* dh = &HS[(size_t)(row0 + rh) * 64 + tc * 8];
            *(float4*)dh       = make_float4(hi[0], hi[1], hi[2], hi[3]);
            *(float4*)(dh + 4) = make_float4(hi[4], hi[5], hi[6], hi[7]);
            if (tc == 0) S[row0 + rh] = sh;
        }
    }
    if (wd0 && tid < 128 && tid < Mloc) {
        D0[row0 + tid] = d0;
        D1[row0 + tid] = d1;
    }
}

// ---------------- per-graph gather-aggregate (warp-level) ----------------
__device__ __forceinline__ void aggr_one(const int* __restrict__ bkt, int deg,
                                         const float* __restrict__ S, float dval,
                                         const float* __restrict__ HS,
                                         int lane, float2* res) {
    float vx = 0.f, vy = 0.f, esum = 0.f;
    for (int base = 0; base < deg; base += 32) {
        int j = base + lane;
        int sidx = 0;
        float e = 0.f;
        if (j < deg) {
            sidx = bkt[j];
            float a = __ldg(&S[sidx]) + dval;
            a = a > 0.f ? a : F_SLOPE * a;
            e = expf(a);
        }
        int cnt = min(32, deg - base);
#pragma unroll 4
        for (int t = 0; t < cnt; t++) {
            float et = __shfl_sync(0xffffffffu, e, t);
            int   st = __shfl_sync(0xffffffffu, sidx, t);
            float2 h = *(const float2*)&HS[st * 64 + lane * 2];
            vx += et * h.x;
            vy += et * h.y;
        }
        esum += e;
    }
#pragma unroll
    for (int off = 16; off; off >>= 1)
        esum += __shfl_xor_sync(0xffffffffu, esum, off);
    if (esum > 0.f) {
        float inv = 1.f / esum;
        res->x += vx * inv;
        res->y += vy * inv;
    }
}

// ---------------- THE mega-kernel ----------------
__global__ void __launch_bounds__(256, 2)
k_mega(const float* __restrict__ x_i, const float* __restrict__ x_e,
       const float* __restrict__ Wsrc_ii, const float* __restrict__ Wdst_ii,
       const float* __restrict__ asrc_ii, const float* __restrict__ adst_ii,
       const float* __restrict__ b_ii,
       const float* __restrict__ Wsrc_ei, const float* __restrict__ Wdst_ei,
       const float* __restrict__ asrc_ei, const float* __restrict__ adst_ei,
       const float* __restrict__ b_ei,
       const float* __restrict__ linW, const float* __restrict__ linb,
       const float* __restrict__ rn,
       const int* __restrict__ eii, const int* __restrict__ eei,
       const int* __restrict__ labels, const int* __restrict__ idxtr,
       const int* __restrict__ chosen,
       float* __restrict__ out, int probN, int writeExtras) {
    extern __shared__ float sm[];
    const int tid = threadIdx.x;
    const int bid = blockIdx.x;
    const int G   = gridDim.x;

    // ===== P0: zero counters/flags + wd vectors =====
    for (int i = bid * 256 + tid; i < N_I; i += G * 256) {
        g_deg_ii[i] = 0;
        g_deg_ei[i] = 0;
        g_trainflag[i] = 0;
        g_invch[i] = -1;
    }
    if (bid == 0 && tid < 128) {
        float s0 = 0.f, s1 = 0.f;
        for (int c = 0; c < HH; c++) {
            s0 += Wdst_ii[tid * HH + c] * adst_ii[c];
            s1 += Wdst_ei[tid * HH + c] * adst_ei[c];
        }
        g_wd_ii[tid] = s0;
        g_wd_ei[tid] = s1;
    }
    gbar();

    // ===== P1: scatter (blocks [0,SB)) || GEMMs (blocks [SB,G)) =====
    if (bid < SB) {
        const int TOT = E_II + E_EI + N_TRAIN + N_CHOSEN;
        for (int idx = bid * 256 + tid; idx < TOT; idx += SB * 256) {
            if (idx < E_II) {
                int d = eii[E_II + idx];
                int pos = atomicAdd(&g_deg_ii[d], 1);
                if (pos < CAP_II) g_bkt_ii[(size_t)d * CAP_II + pos] = eii[idx];
            } else if (idx < E_II + E_EI) {
                int e2 = idx - E_II;
                int d = eei[E_EI + e2];
                int pos = atomicAdd(&g_deg_ei[d], 1);
                if (pos < CAP_EI) g_bkt_ei[(size_t)d * CAP_EI + pos] = eei[e2];
            } else if (idx < E_II + E_EI + N_TRAIN) {
                g_trainflag[idxtr[idx - E_II - E_EI]] = 1;
            } else {
                int j = idx - E_II - E_EI - N_TRAIN;
                g_invch[chosen[j]] = j;
            }
        }
    } else {
        for (int t = bid - SB; t < TII + TEI; t += G - SB) {
            if (t < TII)
                gemm_tile(x_i, Wsrc_ii, asrc_ii, g_wd_ii, g_wd_ei,
                          g_hs_ii, g_s_ii, g_d_ii, g_d_ei, N_I, 128, t * 128, sm);
            else
                gemm_tile(x_e, Wsrc_ei, asrc_ei, nullptr, nullptr,
                          g_hs_ei, g_s_ei, nullptr, nullptr, N_E, 64, (t - TII) * 128, sm);
        }
    }
    gbar();

    // ===== P2: fused aggregation + bias + relu -> emb (+ce/sq for chosen) =====
    {
        const int lane = tid & 31;
        const int nw = G * 8;
        for (int dst = bid * 8 + (tid >> 5); dst < N_I; dst += nw) {
            float2 res = make_float2(0.f, 0.f);
            int deg0 = min(g_deg_ii[dst], CAP_II);
            int deg1 = min(g_deg_ei[dst], CAP_EI);
            aggr_one(&g_bkt_ii[(size_t)dst * CAP_II], deg0, g_s_ii, g_d_ii[dst], g_hs_ii, lane, &res);
            aggr_one(&g_bkt_ei[(size_t)dst * CAP_EI], deg1, g_s_ei, g_d_ei[dst], g_hs_ei, lane, &res);
            int c0 = lane * 2;
            float v0 = 0.5f * (res.x + __ldg(&b_ii[c0])     + __ldg(&b_ei[c0]));
            float v1 = 0.5f * (res.y + __ldg(&b_ii[c0 + 1]) + __ldg(&b_ei[c0 + 1]));
            float2 o;
            o.x = v0 > 0.f ? v0 : 0.f;
            o.y = v1 > 0.f ? v1 : 0.f;
            *(float2*)&g_emb[dst * 64 + c0] = o;
            int ic = g_invch[dst];
            if (ic >= 0) {
                *(float2*)&g_ce[ic * 64 + c0] = o;
                float sq = o.x * o.x + o.y * o.y;
#pragma unroll
                for (int off = 16; off; off >>= 1) sq += __shfl_xor_sync(0xffffffffu, sq, off);
                if (lane == 0) g_sq[ic] = sq;
            }
        }
    }
    gbar();

    // ===== P3: tiled nearest neighbor (blocks handle 8 i's each) =====
    {
        float* tile = sm;            // 64*65
        float* sqj  = sm + 4160;     // 64
        float* cei  = sm + 4224;     // 8*64
        const int wid = tid >> 5, lane = tid & 31;
        for (int ig = bid; ig < N_CHOSEN / 8; ig += G) {
            int i = ig * 8 + wid;
            __syncthreads();
            cei[wid * 64 + lane]      = g_ce[i * 64 + lane];
            cei[wid * 64 + 32 + lane] = g_ce[i * 64 + 32 + lane];
            float sqi = g_sq[i];
            float best = 3.4e38f;
            int bestj = 0x7fffffff;
            for (int tb = 0; tb < N_CHOSEN; tb += 64) {
                __syncthreads();
                for (int idx = tid; idx < 64 * 64; idx += 256) {
                    int j = idx >> 6, k = idx & 63;
                    tile[j * 65 + k] = g_ce[(tb + j) * 64 + k];
                }
                if (tid < 64) sqj[tid] = g_sq[tb + tid];
                __syncthreads();
#pragma unroll
                for (int half = 0; half < 2; half++) {
                    int jl = lane + half * 32;
                    int j = tb + jl;
                    if (j == i) continue;
                    float dot = 0.f;
#pragma unroll 16
                    for (int k = 0; k < 64; k++) dot += cei[wid * 64 + k] * tile[jl * 65 + k];
                    float d2 = sqi + sqj[jl] - 2.f * dot;
                    d2 = d2 > 0.f ? d2 : 0.f;
                    if (d2 < best || (d2 == best && j < bestj)) { best = d2; bestj = j; }
                }
            }
#pragma unroll
            for (int off = 16; off; off >>= 1) {
                float ob = __shfl_down_sync(0xffffffffu, best, off);
                int   oj = __shfl_down_sync(0xffffffffu, bestj, off);
                if (ob < best || (ob == best && oj < bestj)) { best = ob; bestj = oj; }
            }
            if (lane == 0) g_nb[i] = bestj;
        }
    }
    gbar();

    // ===== P4: classifier head + softmax + extras =====
    {
        const int lane = tid & 31;
        const int nw = G * 8;
        for (int n = bid * 8 + (tid >> 5); n < probN; n += nw) {
            float v0, v1;
            if (n < N_I) {
                v0 = g_emb[n * 64 + lane];
                v1 = g_emb[n * 64 + 32 + lane];
            } else {
                int i = n - N_I;
                int nbi = g_nb[i];
                float c0 = g_ce[i * 64 + lane],   c1 = g_ce[i * 64 + 32 + lane];
                float n0 = g_ce[nbi * 64 + lane], n1 = g_ce[nbi * 64 + 32 + lane];
                v0 = c0 + (n0 - c0) * F_INTERP;
                v1 = c1 + (n1 - c1) * F_INTERP;
            }
            float l0 = v0 * __ldg(&linW[lane * 2])     + v1 * __ldg(&linW[(lane + 32) * 2]);
            float l1 = v0 * __ldg(&linW[lane * 2 + 1]) + v1 * __ldg(&linW[(lane + 32) * 2 + 1]);
#pragma unroll
            for (int off = 16; off; off >>= 1) {
                l0 += __shfl_down_sync(0xffffffffu, l0, off);
                l1 += __shfl_down_sync(0xffffffffu, l1, off);
            }
            if (lane == 0) {
                l0 += __ldg(&linb[0]);
                l1 += __ldg(&linb[1]);
                float m = fmaxf(l0, l1);
                float e0 = expf(l0 - m), e1 = expf(l1 - m);
                float inv = 1.f / (e0 + e1);
                out[n * 2]     = e0 * inv;
                out[n * 2 + 1] = e1 * inv;
                if (writeExtras) {
                    int moff = probN * 2;
                    out[moff + n]         = (n >= N_I) ? 1.f : (g_trainflag[n] ? 1.f : 0.f);
                    out[moff + probN + n] = (n < N_I) ? (float)labels[n] : 1.f;
                    float r;
                    if (n < N_I) r = rn[n];
                    else {
                        int i = n - N_I;
                        float rc = rn[chosen[i]];
                        r = rc + (rn[chosen[g_nb[i]]] - rc) * F_INTERP;
                    }
                    out[moff + 2 * probN + n] = r;
                }
            }
        }
    }
}

// ---------------- launch ----------------
extern "C" void kernel_launch(void* const* d_in, const int* in_sizes, int n_in,
                              void* d_out, int out_size) {
    const float* x_i     = (const float*)d_in[0];
    const float* x_e     = (const float*)d_in[1];
    const float* Wsrc_ii = (const float*)d_in[2];
    const float* Wdst_ii = (const float*)d_in[3];
    const float* asrc_ii = (const float*)d_in[4];
    const float* adst_ii = (const float*)d_in[5];
    const float* b_ii    = (const float*)d_in[6];
    // d_in[7..11]: ie branch — unused downstream in the reference; skipped.
    const float* Wsrc_ei = (const float*)d_in[12];
    const float* Wdst_ei = (const float*)d_in[13];
    const float* asrc_ei = (const float*)d_in[14];
    const float* adst_ei = (const float*)d_in[15];
    const float* b_ei    = (const float*)d_in[16];
    const float* linW    = (const float*)d_in[17];
    const float* linb    = (const float*)d_in[18];
    const float* rn      = (const float*)d_in[19];
    const int*   eii     = (const int*)d_in[20];
    const int*   eei     = (const int*)d_in[22];
    const int*   labels  = (const int*)d_in[23];
    const int*   idxtr   = (const int*)d_in[24];
    const int*   chosen  = (const int*)d_in[25];
    float* out = (float*)d_out;

    cudaFuncSetAttribute(k_mega, cudaFuncAttributeMaxDynamicSharedMemorySize, SMEM_BYTES);
    int sms = 0;
    cudaDeviceGetAttribute(&sms, cudaDevAttrMultiProcessorCount, 0);
    int nb = 0;
    cudaOccupancyMaxActiveBlocksPerMultiprocessor(&nb, k_mega, 256, SMEM_BYTES);
    if (nb < 1) nb = 1;
    int G = nb * sms;

    int probN = N_I + N_CHOSEN;
    int writeExtras = (out_size >= probN * 5) ? 1 : 0;
    k_mega<<<G, 256, SMEM_BYTES>>>(
        x_i, x_e, Wsrc_ii, Wdst_ii, asrc_ii, adst_ii, b_ii,
        Wsrc_ei, Wdst_ei, asrc_ei, adst_ei, b_ei,
        linW, linb, rn, eii, eei, labels, idxtr, chosen,
        out, probN, writeExtras);
}

// round 5
// speedup vs baseline: 1.4022x; 1.4022x over previous
#include <cuda_runtime.h>
#include <math.h>

#define N_I 60000
#define N_E 30000
#define DI  128
#define DE  64
#define HH  64
#define E_II 960000
#define E_EI 480000
#define N_TRAIN 2048
#define N_CHOSEN 1024
#define F_INTERP 0.35f
#define F_SLOPE  0.2f
#define CAP_II 64
#define CAP_EI 48
#define TII ((N_I + 127) / 128)   // 469
#define TEI ((N_E + 127) / 128)   // 235
#define SMEM_FLOATS (64*130 + 64*64 + 64 + 256)   // 12736
#define SMEM_BYTES  (SMEM_FLOATS * 4)             // 50944

// ---------------- scratch (static device globals; no allocation) ----------------
__device__ __align__(16) float g_hs_ii[N_I * HH];
__device__ __align__(16) float g_hs_ei[N_E * HH];
__device__ __align__(16) float g_emb[N_I * HH];
__device__ float g_s_ii[N_I];
__device__ float g_d_ii[N_I];
__device__ float g_d_ei[N_I];
__device__ float g_s_ei[N_E];
__device__ int   g_deg_ii[N_I];
__device__ int   g_deg_ei[N_I];
__device__ int   g_bkt_ii[(size_t)N_I * CAP_II];
__device__ int   g_bkt_ei[(size_t)N_I * CAP_EI];
__device__ __align__(16) float g_ce[N_CHOSEN * HH];
__device__ float g_sq[N_CHOSEN];
__device__ int   g_nb[N_CHOSEN];
__device__ int   g_trainflag[N_I];
__device__ int   g_invch[N_I];

// ---------------- packed f32x2 helpers (Blackwell FFMA2) ----------------
__device__ __forceinline__ unsigned long long pk2(float x) {
    unsigned long long r;
    asm("mov.b64 %0, {%1, %1};" : "=l"(r) : "f"(x));
    return r;
}
__device__ __forceinline__ void fma2(unsigned long long& d, unsigned long long a,
                                     unsigned long long b) {
    asm("fma.rn.f32x2 %0, %1, %2, %0;" : "+l"(d) : "l"(a), "l"(b));
}
__device__ __forceinline__ void upk(unsigned long long v, float& lo, float& hi) {
    asm("mov.b64 {%0, %1}, %2;" : "=f"(lo), "=f"(hi) : "l"(v));
}

// ---------------- GEMM tile (256 threads): HS = A@W, S = HS@asrc, D = A@wd ----------------
// BM=128, BN=64, K chunked by 64. Thread (tr,tc): rows 4tr..4tr+3 x cols 8tc..8tc+7.
// If Wdst != nullptr, wd vectors are computed in-block (wd = Wdst @ adst).
__device__ void gemm_tile(const float* __restrict__ A, const float* __restrict__ W,
                          const float* __restrict__ asrc,
                          const float* __restrict__ Wdst0, const float* __restrict__ adst0,
                          const float* __restrict__ Wdst1, const float* __restrict__ adst1,
                          float* __restrict__ HS, float* __restrict__ S,
                          float* __restrict__ D0, float* __restrict__ D1,
                          int M, int K, int row0, float* sm) {
    float* As  = sm;              // [64][130]
    float* Ws  = sm + 64 * 130;   // [64][64]
    float* asc = Ws + 64 * 64;    // [64]
    float* wds = asc + 64;        // [256]  (wd0, wd1 each up to 128)

    const int tid  = threadIdx.x;
    const int Mloc = M - row0;
    const int tr = tid >> 3;      // 0..31
    const int tc = tid & 7;       // 0..7

    // compute wd in-block (Wdst rows are L2-resident, shared by all blocks)
    if (Wdst0 && tid < K) {
        float s0 = 0.f, s1 = 0.f;
#pragma unroll 16
        for (int c = 0; c < HH; c++) {
            s0 += __ldg(&Wdst0[tid * HH + c]) * __ldg(&adst0[c]);
            s1 += __ldg(&Wdst1[tid * HH + c]) * __ldg(&adst1[c]);
        }
        wds[tid]     = s0;
        wds[128 + tid] = s1;
    }
    if (tid < 64) asc[tid] = asrc[tid];

    unsigned long long acc[2][8];
#pragma unroll
    for (int p = 0; p < 2; p++)
#pragma unroll
        for (int j = 0; j < 8; j++) acc[p][j] = 0ull;
    float d0 = 0.f, d1 = 0.f;

    const int nch = K >> 6;
    for (int ch = 0; ch < nch; ch++) {
        const int kk = ch << 6;
        __syncthreads();
        for (int i = tid; i < 128 * 64; i += 256) {
            int r = i >> 6, k = i & 63;
            As[k * 130 + r] = (r < Mloc) ? A[(size_t)(row0 + r) * K + kk + k] : 0.f;
        }
        for (int i = tid; i < 64 * 64; i += 256) Ws[i] = W[kk * 64 + i];
        __syncthreads();

        const float* AsB = As + tr * 4;
        const float* WsB = Ws + tc * 8;
        for (int k = 0; k < 64; k++) {
            unsigned long long a0 = *(const unsigned long long*)(AsB + k * 130);
            unsigned long long a1 = *(const unsigned long long*)(AsB + k * 130 + 2);
            float4 b0 = *(const float4*)(WsB + k * 64);
            float4 b1 = *(const float4*)(WsB + k * 64 + 4);
            unsigned long long bd[8];
            bd[0] = pk2(b0.x); bd[1] = pk2(b0.y); bd[2] = pk2(b0.z); bd[3] = pk2(b0.w);
            bd[4] = pk2(b1.x); bd[5] = pk2(b1.y); bd[6] = pk2(b1.z); bd[7] = pk2(b1.w);
#pragma unroll
            for (int j = 0; j < 8; j++) {
                fma2(acc[0][j], a0, bd[j]);
                fma2(acc[1][j], a1, bd[j]);
            }
        }
        if (Wdst0 && tid < 128 && tid < Mloc) {
            for (int k = 0; k < 64; k++) {
                float a = As[k * 130 + tid];
                d0 += a * wds[kk + k];
                d1 += a * wds[128 + kk + k];
            }
        }
    }

    float ar[8];
#pragma unroll
    for (int j = 0; j < 8; j++) ar[j] = asc[tc * 8 + j];

#pragma unroll
    for (int p = 0; p < 2; p++) {
        float lo[8], hi[8];
#pragma unroll
        for (int j = 0; j < 8; j++) upk(acc[p][j], lo[j], hi[j]);
        int rl = tr * 4 + 2 * p;
        int rh = rl + 1;
        float sl = lo[0]*ar[0]+lo[1]*ar[1]+lo[2]*ar[2]+lo[3]*ar[3]+lo[4]*ar[4]+lo[5]*ar[5]+lo[6]*ar[6]+lo[7]*ar[7];
        float sh = hi[0]*ar[0]+hi[1]*ar[1]+hi[2]*ar[2]+hi[3]*ar[3]+hi[4]*ar[4]+hi[5]*ar[5]+hi[6]*ar[6]+hi[7]*ar[7];
#pragma unroll
        for (int off = 4; off; off >>= 1) {
            sl += __shfl_down_sync(0xffffffffu, sl, off, 8);
            sh += __shfl_down_sync(0xffffffffu, sh, off, 8);
        }
        if (rl < Mloc) {
            float* dl = &HS[(size_t)(row0 + rl) * 64 + tc * 8];
            *(float4*)dl       = make_float4(lo[0], lo[1], lo[2], lo[3]);
            *(float4*)(dl + 4) = make_float4(lo[4], lo[5], lo[6], lo[7]);
            if (tc == 0) S[row0 + rl] = sl;
        }
        if (rh < Mloc) {
            float* dh = &HS[(size_t)(row0 + rh) * 64 + tc * 8];
            *(float4*)dh       = make_float4(hi[0], hi[1], hi[2], hi[3]);
            *(float4*)(dh + 4) = make_float4(hi[4], hi[5], hi[6], hi[7]);
            if (tc == 0) S[row0 + rh] = sh;
        }
    }
    if (Wdst0 && tid < 128 && tid < Mloc) {
        D0[row0 + tid] = d0;
        D1[row0 + tid] = d1;
    }
}

// ---------------- combined GEMM launch (both matrices, one grid) ----------------
__global__ void __launch_bounds__(256, 2)
k_gemm_all(const float* __restrict__ x_i, const float* __restrict__ Wsrc_ii,
           const float* __restrict__ asrc_ii,
           const float* __restrict__ Wdst_ii, const float* __restrict__ adst_ii,
           const float* __restrict__ Wdst_ei, const float* __restrict__ adst_ei,
           const float* __restrict__ x_e, const float* __restrict__ Wsrc_ei,
           const float* __restrict__ asrc_ei) {
    extern __shared__ float sm[];
    int t = blockIdx.x;
    if (t < TII)
        gemm_tile(x_i, Wsrc_ii, asrc_ii, Wdst_ii, adst_ii, Wdst_ei, adst_ei,
                  g_hs_ii, g_s_ii, g_d_ii, g_d_ei, N_I, 128, t * 128, sm);
    else
        gemm_tile(x_e, Wsrc_ei, asrc_ei, nullptr, nullptr, nullptr, nullptr,
                  g_hs_ei, g_s_ei, nullptr, nullptr, N_E, 64, (t - TII) * 128, sm);
}

// ---------------- scatter: buckets + trainflag + invchosen in one launch ----------------
__global__ void k_scatter2(const int* __restrict__ eii, const int* __restrict__ eei,
                           const int* __restrict__ idxtr, const int* __restrict__ chosen) {
    int idx = blockIdx.x * blockDim.x + threadIdx.x;
    if (idx < E_II) {
        int d = eii[E_II + idx];
        int pos = atomicAdd(&g_deg_ii[d], 1);
        if (pos < CAP_II) g_bkt_ii[(size_t)d * CAP_II + pos] = eii[idx];
    } else if (idx < E_II + E_EI) {
        int e2 = idx - E_II;
        int d = eei[E_EI + e2];
        int pos = atomicAdd(&g_deg_ei[d], 1);
        if (pos < CAP_EI) g_bkt_ei[(size_t)d * CAP_EI + pos] = eei[e2];
    } else if (idx < E_II + E_EI + N_TRAIN) {
        g_trainflag[idxtr[idx - E_II - E_EI]] = 1;
    } else if (idx < E_II + E_EI + N_TRAIN + N_CHOSEN) {
        int j = idx - E_II - E_EI - N_TRAIN;
        g_invch[chosen[j]] = j;
    }
}

// ---------------- per-graph gather-aggregate (warp-level) ----------------
__device__ __forceinline__ void aggr_one(const int* __restrict__ bkt, int deg,
                                         const float* __restrict__ S, float dval,
                                         const float* __restrict__ HS,
                                         int lane, float2* res) {
    float vx = 0.f, vy = 0.f, esum = 0.f;
    for (int base = 0; base < deg; base += 32) {
        int j = base + lane;
        int sidx = 0;
        float e = 0.f;
        if (j < deg) {
            sidx = bkt[j];
            float a = __ldg(&S[sidx]) + dval;
            a = a > 0.f ? a : F_SLOPE * a;
            e = expf(a);
        }
        int cnt = min(32, deg - base);
#pragma unroll 4
        for (int t = 0; t < cnt; t++) {
            float et = __shfl_sync(0xffffffffu, e, t);
            int   st = __shfl_sync(0xffffffffu, sidx, t);
            float2 h = *(const float2*)&HS[st * 64 + lane * 2];
            vx += et * h.x;
            vy += et * h.y;
        }
        esum += e;
    }
#pragma unroll
    for (int off = 16; off; off >>= 1)
        esum += __shfl_xor_sync(0xffffffffu, esum, off);
    if (esum > 0.f) {
        float inv = 1.f / esum;
        res->x += vx * inv;
        res->y += vy * inv;
    }
}

// ---------------- fused aggregation + bias + relu -> emb (+ce/sq for chosen) ----------------
__global__ void k_aggr(const float* __restrict__ b_ii, const float* __restrict__ b_ei) {
    int dst = blockIdx.x * (blockDim.x >> 5) + (threadIdx.x >> 5);
    int lane = threadIdx.x & 31;
    if (dst >= N_I) return;

    float2 res = make_float2(0.f, 0.f);
    int deg0 = min(g_deg_ii[dst], CAP_II);
    int deg1 = min(g_deg_ei[dst], CAP_EI);
    aggr_one(&g_bkt_ii[(size_t)dst * CAP_II], deg0, g_s_ii, g_d_ii[dst], g_hs_ii, lane, &res);
    aggr_one(&g_bkt_ei[(size_t)dst * CAP_EI], deg1, g_s_ei, g_d_ei[dst], g_hs_ei, lane, &res);

    int c0 = lane * 2;
    float v0 = 0.5f * (res.x + __ldg(&b_ii[c0])     + __ldg(&b_ei[c0]));
    float v1 = 0.5f * (res.y + __ldg(&b_ii[c0 + 1]) + __ldg(&b_ei[c0 + 1]));
    float2 o;
    o.x = v0 > 0.f ? v0 : 0.f;
    o.y = v1 > 0.f ? v1 : 0.f;
    *(float2*)&g_emb[dst * 64 + c0] = o;
    int ic = g_invch[dst];
    if (ic >= 0) {
        *(float2*)&g_ce[ic * 64 + c0] = o;
        float sq = o.x * o.x + o.y * o.y;
#pragma unroll
        for (int off = 16; off; off >>= 1) sq += __shfl_xor_sync(0xffffffffu, sq, off);
        if (lane == 0) g_sq[ic] = sq;
    }
}

// ---------------- tiled nearest neighbor: 8 i's per block share j-tiles ----------------
__global__ void k_nn2() {
    __shared__ float tile[64 * 65];
    __shared__ float sqj[64];
    __shared__ float cei[8 * 64];
    int tid = threadIdx.x;
    int wid = tid >> 5, lane = tid & 31;
    int i = blockIdx.x * 8 + wid;

    cei[wid * 64 + lane]      = g_ce[i * 64 + lane];
    cei[wid * 64 + 32 + lane] = g_ce[i * 64 + 32 + lane];
    float sqi = g_sq[i];
    float best = 3.4e38f;
    int bestj = 0x7fffffff;

    for (int tb = 0; tb < N_CHOSEN; tb += 64) {
        __syncthreads();
        for (int idx = tid; idx < 64 * 64; idx += 256) {
            int j = idx >> 6, k = idx & 63;
            tile[j * 65 + k] = g_ce[(tb + j) * 64 + k];
        }
        if (tid < 64) sqj[tid] = g_sq[tb + tid];
        __syncthreads();

#pragma unroll
        for (int half = 0; half < 2; half++) {
            int jl = lane + half * 32;
            int j = tb + jl;
            if (j == i) continue;
            float dot = 0.f;
#pragma unroll 16
            for (int k = 0; k < 64; k++) dot += cei[wid * 64 + k] * tile[jl * 65 + k];
            float d2 = sqi + sqj[jl] - 2.f * dot;
            d2 = d2 > 0.f ? d2 : 0.f;
            if (d2 < best || (d2 == best && j < bestj)) { best = d2; bestj = j; }
        }
    }
#pragma unroll
    for (int off = 16; off; off >>= 1) {
        float ob = __shfl_down_sync(0xffffffffu, best, off);
        int   oj = __shfl_down_sync(0xffffffffu, bestj, off);
        if (ob < best || (ob == best && oj < bestj)) { best = ob; bestj = oj; }
    }
    if (lane == 0) g_nb[i] = bestj;
}

// ---------------- classifier head + softmax + extras (uses trainflag) ----------------
__global__ void k_final(const float* __restrict__ linW, const float* __restrict__ linb,
                        const float* __restrict__ rn, const int* __restrict__ labels,
                        const int* __restrict__ chosen,
                        float* __restrict__ out, int probN, int writeExtras) {
    int n = blockIdx.x * (blockDim.x >> 5) + (threadIdx.x >> 5);
    int lane = threadIdx.x & 31;
    if (n >= probN) return;
    float v0, v1;
    if (n < N_I) {
        v0 = g_emb[n * 64 + lane];
        v1 = g_emb[n * 64 + 32 + lane];
    } else {
        int i = n - N_I;
        int nbi = g_nb[i];
        float c0 = g_ce[i * 64 + lane],   c1 = g_ce[i * 64 + 32 + lane];
        float n0 = g_ce[nbi * 64 + lane], n1 = g_ce[nbi * 64 + 32 + lane];
        v0 = c0 + (n0 - c0) * F_INTERP;
        v1 = c1 + (n1 - c1) * F_INTERP;
    }
    float l0 = v0 * __ldg(&linW[lane * 2])     + v1 * __ldg(&linW[(lane + 32) * 2]);
    float l1 = v0 * __ldg(&linW[lane * 2 + 1]) + v1 * __ldg(&linW[(lane + 32) * 2 + 1]);
#pragma unroll
    for (int off = 16; off; off >>= 1) {
        l0 += __shfl_down_sync(0xffffffffu, l0, off);
        l1 += __shfl_down_sync(0xffffffffu, l1, off);
    }
    if (lane == 0) {
        l0 += __ldg(&linb[0]);
        l1 += __ldg(&linb[1]);
        float m = fmaxf(l0, l1);
        float e0 = expf(l0 - m), e1 = expf(l1 - m);
        float inv = 1.f / (e0 + e1);
        out[n * 2]     = e0 * inv;
        out[n * 2 + 1] = e1 * inv;
        if (writeExtras) {
            int moff = probN * 2;
            out[moff + n]         = (n >= N_I) ? 1.f : (g_trainflag[n] ? 1.f : 0.f);
            out[moff + probN + n] = (n < N_I) ? (float)labels[n] : 1.f;
            float r;
            if (n < N_I) r = rn[n];
            else {
                int i = n - N_I;
                float rc = rn[chosen[i]];
                r = rc + (rn[chosen[g_nb[i]]] - rc) * F_INTERP;
            }
            out[moff + 2 * probN + n] = r;
        }
    }
}

// ---------------- launch ----------------
extern "C" void kernel_launch(void* const* d_in, const int* in_sizes, int n_in,
                              void* d_out, int out_size) {
    const float* x_i     = (const float*)d_in[0];
    const float* x_e     = (const float*)d_in[1];
    const float* Wsrc_ii = (const float*)d_in[2];
    const float* Wdst_ii = (const float*)d_in[3];
    const float* asrc_ii = (const float*)d_in[4];
    const float* adst_ii = (const float*)d_in[5];
    const float* b_ii    = (const float*)d_in[6];
    // d_in[7..11]: ie branch — unused downstream in the reference; skipped.
    const float* Wsrc_ei = (const float*)d_in[12];
    const float* Wdst_ei = (const float*)d_in[13];
    const float* asrc_ei = (const float*)d_in[14];
    const float* adst_ei = (const float*)d_in[15];
    const float* b_ei    = (const float*)d_in[16];
    const float* linW    = (const float*)d_in[17];
    const float* linb    = (const float*)d_in[18];
    const float* rn      = (const float*)d_in[19];
    const int*   eii     = (const int*)d_in[20];
    const int*   eei     = (const int*)d_in[22];
    const int*   labels  = (const int*)d_in[23];
    const int*   idxtr   = (const int*)d_in[24];
    const int*   chosen  = (const int*)d_in[25];
    float* out = (float*)d_out;

    void *p_deg_ii, *p_deg_ei, *p_tf, *p_iv;
    cudaGetSymbolAddress(&p_deg_ii, g_deg_ii);
    cudaGetSymbolAddress(&p_deg_ei, g_deg_ei);
    cudaGetSymbolAddress(&p_tf, g_trainflag);
    cudaGetSymbolAddress(&p_iv, g_invch);

    cudaMemsetAsync(p_deg_ii, 0, (size_t)N_I * sizeof(int));
    cudaMemsetAsync(p_deg_ei, 0, (size_t)N_I * sizeof(int));
    cudaMemsetAsync(p_tf, 0, (size_t)N_I * sizeof(int));
    cudaMemsetAsync(p_iv, 0xFF, (size_t)N_I * sizeof(int));   // -1

    const int SCT = E_II + E_EI + N_TRAIN + N_CHOSEN;
    k_scatter2<<<(SCT + 255) / 256, 256>>>(eii, eei, idxtr, chosen);

    cudaFuncSetAttribute(k_gemm_all, cudaFuncAttributeMaxDynamicSharedMemorySize, SMEM_BYTES);
    k_gemm_all<<<TII + TEI, 256, SMEM_BYTES>>>(
        x_i, Wsrc_ii, asrc_ii, Wdst_ii, adst_ii, Wdst_ei, adst_ei,
        x_e, Wsrc_ei, asrc_ei);

    k_aggr<<<(N_I + 7) / 8, 256>>>(b_ii, b_ei);

    k_nn2<<<N_CHOSEN / 8, 256>>>();

    int probN = N_I + N_CHOSEN;
    int writeExtras = (out_size >= probN * 5) ? 1 : 0;
    k_final<<<(probN + 7) / 8, 256>>>(linW, linb, rn, labels, chosen, out, probN, writeExtras);
}

// round 7
// speedup vs baseline: 1.4991x; 1.0691x over previous
#include <cuda_runtime.h>
#include <math.h>

#define N_I 60000
#define N_E 30000
#define DI  128
#define DE  64
#define HH  64
#define E_II 960000
#define E_EI 480000
#define N_TRAIN 2048
#define N_CHOSEN 1024
#define F_INTERP 0.35f
#define F_SLOPE  0.2f
#define CAP_II 64
#define CAP_EI 48
#define TII ((N_I + 127) / 128)   // 469
#define TEI ((N_E + 127) / 128)   // 235
#define SCB 128                   // scatter blocks prepended to gemm grid
#define SMEM_FLOATS (64*130 + 64*64 + 64 + 256)   // 12736
#define SMEM_BYTES  (SMEM_FLOATS * 4)             // 50944

// ---------------- scratch (static device globals; no allocation) ----------------
__device__ __align__(16) float g_hs_ii[N_I * HH];
__device__ __align__(16) float g_hs_ei[N_E * HH];
__device__ __align__(16) float g_emb[N_I * HH];
__device__ float g_s_ii[N_I];
__device__ float g_d_ii[N_I];
__device__ float g_d_ei[N_I];
__device__ float g_s_ei[N_E];
__device__ int   g_deg_ii[N_I];
__device__ int   g_deg_ei[N_I];
__device__ int   g_bkt_ii[(size_t)N_I * CAP_II];
__device__ int   g_bkt_ei[(size_t)N_I * CAP_EI];
__device__ __align__(16) float g_ce[N_CHOSEN * HH];
__device__ float g_sq[N_CHOSEN];
__device__ unsigned long long g_nbpack[N_CHOSEN];
__device__ int   g_trainflag[N_I];
__device__ int   g_invch[N_I];

// ---------------- packed f32x2 helpers (Blackwell FFMA2) ----------------
__device__ __forceinline__ unsigned long long pk2(float x) {
    unsigned long long r;
    asm("mov.b64 %0, {%1, %1};" : "=l"(r) : "f"(x));
    return r;
}
__device__ __forceinline__ void fma2(unsigned long long& d, unsigned long long a,
                                     unsigned long long b) {
    asm("fma.rn.f32x2 %0, %1, %2, %0;" : "+l"(d) : "l"(a), "l"(b));
}
__device__ __forceinline__ void upk(unsigned long long v, float& lo, float& hi) {
    asm("mov.b64 {%0, %1}, %2;" : "=f"(lo), "=f"(hi) : "l"(v));
}

// ---------------- GEMM tile (256 threads): HS = A@W, S = HS@asrc, D = A@wd ----------------
__device__ void gemm_tile(const float* __restrict__ A, const float* __restrict__ W,
                          const float* __restrict__ asrc,
                          const float* __restrict__ Wdst0, const float* __restrict__ adst0,
                          const float* __restrict__ Wdst1, const float* __restrict__ adst1,
                          float* __restrict__ HS, float* __restrict__ S,
                          float* __restrict__ D0, float* __restrict__ D1,
                          int M, int K, int row0, float* sm) {
    float* As  = sm;              // [64][130]
    float* Ws  = sm + 64 * 130;   // [64][64]
    float* asc = Ws + 64 * 64;    // [64]
    float* wds = asc + 64;        // [256]

    const int tid  = threadIdx.x;
    const int Mloc = M - row0;
    const int tr = tid >> 3;      // 0..31
    const int tc = tid & 7;       // 0..7

    if (Wdst0 && tid < K) {
        float s0 = 0.f, s1 = 0.f;
#pragma unroll 16
        for (int c = 0; c < HH; c++) {
            s0 += __ldg(&Wdst0[tid * HH + c]) * __ldg(&adst0[c]);
            s1 += __ldg(&Wdst1[tid * HH + c]) * __ldg(&adst1[c]);
        }
        wds[tid]       = s0;
        wds[128 + tid] = s1;
    }
    if (tid < 64) asc[tid] = asrc[tid];

    unsigned long long acc[2][8];
#pragma unroll
    for (int p = 0; p < 2; p++)
#pragma unroll
        for (int j = 0; j < 8; j++) acc[p][j] = 0ull;
    float d0 = 0.f, d1 = 0.f;

    const int nch = K >> 6;
    for (int ch = 0; ch < nch; ch++) {
        const int kk = ch << 6;
        __syncthreads();
        for (int i = tid; i < 128 * 64; i += 256) {
            int r = i >> 6, k = i & 63;
            As[k * 130 + r] = (r < Mloc) ? A[(size_t)(row0 + r) * K + kk + k] : 0.f;
        }
        for (int i = tid; i < 64 * 64; i += 256) Ws[i] = W[kk * 64 + i];
        __syncthreads();

        const float* AsB = As + tr * 4;
        const float* WsB = Ws + tc * 8;
        for (int k = 0; k < 64; k++) {
            unsigned long long a0 = *(const unsigned long long*)(AsB + k * 130);
            unsigned long long a1 = *(const unsigned long long*)(AsB + k * 130 + 2);
            float4 b0 = *(const float4*)(WsB + k * 64);
            float4 b1 = *(const float4*)(WsB + k * 64 + 4);
            unsigned long long bd[8];
            bd[0] = pk2(b0.x); bd[1] = pk2(b0.y); bd[2] = pk2(b0.z); bd[3] = pk2(b0.w);
            bd[4] = pk2(b1.x); bd[5] = pk2(b1.y); bd[6] = pk2(b1.z); bd[7] = pk2(b1.w);
#pragma unroll
            for (int j = 0; j < 8; j++) {
                fma2(acc[0][j], a0, bd[j]);
                fma2(acc[1][j], a1, bd[j]);
            }
        }
        if (Wdst0 && tid < 128 && tid < Mloc) {
            for (int k = 0; k < 64; k++) {
                float a = As[k * 130 + tid];
                d0 += a * wds[kk + k];
                d1 += a * wds[128 + kk + k];
            }
        }
    }

    float ar[8];
#pragma unroll
    for (int j = 0; j < 8; j++) ar[j] = asc[tc * 8 + j];

#pragma unroll
    for (int p = 0; p < 2; p++) {
        float lo[8], hi[8];
#pragma unroll
        for (int j = 0; j < 8; j++) upk(acc[p][j], lo[j], hi[j]);
        int rl = tr * 4 + 2 * p;
        int rh = rl + 1;
        float sl = lo[0]*ar[0]+lo[1]*ar[1]+lo[2]*ar[2]+lo[3]*ar[3]+lo[4]*ar[4]+lo[5]*ar[5]+lo[6]*ar[6]+lo[7]*ar[7];
        float sh = hi[0]*ar[0]+hi[1]*ar[1]+hi[2]*ar[2]+hi[3]*ar[3]+hi[4]*ar[4]+hi[5]*ar[5]+hi[6]*ar[6]+hi[7]*ar[7];
#pragma unroll
        for (int off = 4; off; off >>= 1) {
            sl += __shfl_down_sync(0xffffffffu, sl, off, 8);
            sh += __shfl_down_sync(0xffffffffu, sh, off, 8);
        }
        if (rl < Mloc) {
            float* dl = &HS[(size_t)(row0 + rl) * 64 + tc * 8];
            *(float4*)dl       = make_float4(lo[0], lo[1], lo[2], lo[3]);
            *(float4*)(dl + 4) = make_float4(lo[4], lo[5], lo[6], lo[7]);
            if (tc == 0) S[row0 + rl] = sl;
        }
        if (rh < Mloc) {
            float* dh = &HS[(size_t)(row0 + rh) * 64 + tc * 8];
            *(float4*)dh       = make_float4(hi[0], hi[1], hi[2], hi[3]);
            *(float4*)(dh + 4) = make_float4(hi[4], hi[5], hi[6], hi[7]);
            if (tc == 0) S[row0 + rh] = sh;
        }
    }
    if (Wdst0 && tid < 128 && tid < Mloc) {
        D0[row0 + tid] = d0;
        D1[row0 + tid] = d1;
    }
}

// ---------------- combined launch: scatter blocks [0,SCB) || GEMM blocks [SCB,..) ---------
__global__ void __launch_bounds__(256, 2)
k_gemm_all(const float* __restrict__ x_i, const float* __restrict__ Wsrc_ii,
           const float* __restrict__ asrc_ii,
           const float* __restrict__ Wdst_ii, const float* __restrict__ adst_ii,
           const float* __restrict__ Wdst_ei, const float* __restrict__ adst_ei,
           const float* __restrict__ x_e, const float* __restrict__ Wsrc_ei,
           const float* __restrict__ asrc_ei,
           const int* __restrict__ eii, const int* __restrict__ eei,
           const int* __restrict__ idxtr, const int* __restrict__ chosen) {
    extern __shared__ float sm[];
    const int bid = blockIdx.x;
    if (bid < SCB) {
        const int TOT = E_II + E_EI + N_TRAIN + N_CHOSEN + N_CHOSEN;
        for (int idx = bid * 256 + threadIdx.x; idx < TOT; idx += SCB * 256) {
            if (idx < E_II) {
                int d = eii[E_II + idx];
                int pos = atomicAdd(&g_deg_ii[d], 1);
                if (pos < CAP_II) g_bkt_ii[(size_t)d * CAP_II + pos] = eii[idx];
            } else if (idx < E_II + E_EI) {
                int e2 = idx - E_II;
                int d = eei[E_EI + e2];
                int pos = atomicAdd(&g_deg_ei[d], 1);
                if (pos < CAP_EI) g_bkt_ei[(size_t)d * CAP_EI + pos] = eei[e2];
            } else if (idx < E_II + E_EI + N_TRAIN) {
                g_trainflag[idxtr[idx - E_II - E_EI]] = 1;
            } else if (idx < E_II + E_EI + N_TRAIN + N_CHOSEN) {
                int j = idx - E_II - E_EI - N_TRAIN;
                g_invch[chosen[j]] = j;
            } else {
                g_nbpack[idx - E_II - E_EI - N_TRAIN - N_CHOSEN] = 0xFFFFFFFFFFFFFFFFull;
            }
        }
        return;
    }
    int t = bid - SCB;
    if (t < TII)
        gemm_tile(x_i, Wsrc_ii, asrc_ii, Wdst_ii, adst_ii, Wdst_ei, adst_ei,
                  g_hs_ii, g_s_ii, g_d_ii, g_d_ei, N_I, 128, t * 128, sm);
    else
        gemm_tile(x_e, Wsrc_ei, asrc_ei, nullptr, nullptr, nullptr, nullptr,
                  g_hs_ei, g_s_ei, nullptr, nullptr, N_E, 64, (t - TII) * 128, sm);
}

// ---------------- per-graph gather-aggregate (warp-level) ----------------
__device__ __forceinline__ void aggr_one(const int* __restrict__ bkt, int deg,
                                         const float* __restrict__ S, float dval,
                                         const float* __restrict__ HS,
                                         int lane, float2* res) {
    float vx = 0.f, vy = 0.f, esum = 0.f;
    for (int base = 0; base < deg; base += 32) {
        int j = base + lane;
        int sidx = 0;
        float e = 0.f;
        if (j < deg) {
            sidx = bkt[j];
            float a = __ldg(&S[sidx]) + dval;
            a = a > 0.f ? a : F_SLOPE * a;
            e = expf(a);
        }
        int cnt = min(32, deg - base);
#pragma unroll 4
        for (int t = 0; t < cnt; t++) {
            float et = __shfl_sync(0xffffffffu, e, t);
            int   st = __shfl_sync(0xffffffffu, sidx, t);
            float2 h = *(const float2*)&HS[st * 64 + lane * 2];
            vx += et * h.x;
            vy += et * h.y;
        }
        esum += e;
    }
#pragma unroll
    for (int off = 16; off; off >>= 1)
        esum += __shfl_xor_sync(0xffffffffu, esum, off);
    if (esum > 0.f) {
        float inv = 1.f / esum;
        res->x += vx * inv;
        res->y += vy * inv;
    }
}

// ---------------- fused aggregation + bias + relu -> emb (+ce/sq for chosen) ----------------
__global__ void k_aggr(const float* __restrict__ b_ii, const float* __restrict__ b_ei) {
    int dst = blockIdx.x * (blockDim.x >> 5) + (threadIdx.x >> 5);
    int lane = threadIdx.x & 31;
    if (dst >= N_I) return;

    float2 res = make_float2(0.f, 0.f);
    int deg0 = min(g_deg_ii[dst], CAP_II);
    int deg1 = min(g_deg_ei[dst], CAP_EI);
    aggr_one(&g_bkt_ii[(size_t)dst * CAP_II], deg0, g_s_ii, g_d_ii[dst], g_hs_ii, lane, &res);
    aggr_one(&g_bkt_ei[(size_t)dst * CAP_EI], deg1, g_s_ei, g_d_ei[dst], g_hs_ei, lane, &res);

    int c0 = lane * 2;
    float v0 = 0.5f * (res.x + __ldg(&b_ii[c0])     + __ldg(&b_ei[c0]));
    float v1 = 0.5f * (res.y + __ldg(&b_ii[c0 + 1]) + __ldg(&b_ei[c0 + 1]));
    float2 o;
    o.x = v0 > 0.f ? v0 : 0.f;
    o.y = v1 > 0.f ? v1 : 0.f;
    *(float2*)&g_emb[dst * 64 + c0] = o;
    int ic = g_invch[dst];
    if (ic >= 0) {
        *(float2*)&g_ce[ic * 64 + c0] = o;
        float sq = o.x * o.x + o.y * o.y;
#pragma unroll
        for (int off = 16; off; off >>= 1) sq += __shfl_xor_sync(0xffffffffu, sq, off);
        if (lane == 0) g_sq[ic] = sq;
    }
}

// ---------------- NN: block = 8 i's x 256-j chunk; packed atomicMin merge ----------------
__global__ void k_nn3() {
    __shared__ float tile[64 * 65];
    __shared__ float sqj[64];
    __shared__ float cei[8 * 64];
    int tid = threadIdx.x;
    int wid = tid >> 5, lane = tid & 31;
    int i = (blockIdx.x >> 2) * 8 + wid;
    int jbase = (blockIdx.x & 3) * 256;

    cei[wid * 64 + lane]      = g_ce[i * 64 + lane];
    cei[wid * 64 + 32 + lane] = g_ce[i * 64 + 32 + lane];
    const float sqi = g_sq[i];
    float best = 3.4e38f;
    int bestj = 0x7fffffff;

    for (int tb = jbase; tb < jbase + 256; tb += 64) {
        __syncthreads();
        for (int idx = tid; idx < 64 * 64; idx += 256) {
            int j = idx >> 6, k = idx & 63;
            tile[j * 65 + k] = g_ce[(tb + j) * 64 + k];
        }
        if (tid < 64) sqj[tid] = g_sq[tb + tid];
        __syncthreads();

#pragma unroll
        for (int half = 0; half < 2; half++) {
            int jl = lane + half * 32;
            int j = tb + jl;
            if (j == i) continue;
            float dot = 0.f;
#pragma unroll 16
            for (int k = 0; k < 64; k++) dot += cei[wid * 64 + k] * tile[jl * 65 + k];
            float d2 = sqi + sqj[jl] - 2.f * dot;
            d2 = d2 > 0.f ? d2 : 0.f;
            if (d2 < best || (d2 == best && j < bestj)) { best = d2; bestj = j; }
        }
    }
#pragma unroll
    for (int off = 16; off; off >>= 1) {
        float ob = __shfl_down_sync(0xffffffffu, best, off);
        int   oj = __shfl_down_sync(0xffffffffu, bestj, off);
        if (ob < best || (ob == best && oj < bestj)) { best = ob; bestj = oj; }
    }
    if (lane == 0) {
        unsigned long long pk = ((unsigned long long)__float_as_uint(best) << 32) |
                                (unsigned)bestj;
        atomicMin(&g_nbpack[i], pk);
    }
}

// ---------------- classifier head + softmax + extras ----------------
__global__ void k_final(const float* __restrict__ linW, const float* __restrict__ linb,
                        const float* __restrict__ rn, const int* __restrict__ labels,
                        const int* __restrict__ chosen,
                        float* __restrict__ out, int probN, int writeExtras) {
    int n = blockIdx.x * (blockDim.x >> 5) + (threadIdx.x >> 5);
    int lane = threadIdx.x & 31;
    if (n >= probN) return;
    float v0, v1;
    if (n < N_I) {
        v0 = g_emb[n * 64 + lane];
        v1 = g_emb[n * 64 + 32 + lane];
    } else {
        int i = n - N_I;
        int nbi = (int)(g_nbpack[i] & 0xFFFFFFFFull);
        float c0 = g_ce[i * 64 + lane],   c1 = g_ce[i * 64 + 32 + lane];
        float n0 = g_ce[nbi * 64 + lane], n1 = g_ce[nbi * 64 + 32 + lane];
        v0 = c0 + (n0 - c0) * F_INTERP;
        v1 = c1 + (n1 - c1) * F_INTERP;
    }
    float l0 = v0 * __ldg(&linW[lane * 2])     + v1 * __ldg(&linW[(lane + 32) * 2]);
    float l1 = v0 * __ldg(&linW[lane * 2 + 1]) + v1 * __ldg(&linW[(lane + 32) * 2 + 1]);
#pragma unroll
    for (int off = 16; off; off >>= 1) {
        l0 += __shfl_down_sync(0xffffffffu, l0, off);
        l1 += __shfl_down_sync(0xffffffffu, l1, off);
    }
    if (lane == 0) {
        l0 += __ldg(&linb[0]);
        l1 += __ldg(&linb[1]);
        float m = fmaxf(l0, l1);
        float e0 = expf(l0 - m), e1 = expf(l1 - m);
        float inv = 1.f / (e0 + e1);
        out[n * 2]     = e0 * inv;
        out[n * 2 + 1] = e1 * inv;
        if (writeExtras) {
            int moff = probN * 2;
            out[moff + n]         = (n >= N_I) ? 1.f : (g_trainflag[n] ? 1.f : 0.f);
            out[moff + probN + n] = (n < N_I) ? (float)labels[n] : 1.f;
            float r;
            if (n < N_I) r = rn[n];
            else {
                int i = n - N_I;
                int nbi = (int)(g_nbpack[i] & 0xFFFFFFFFull);
                float rc = rn[chosen[i]];
                r = rc + (rn[chosen[nbi]] - rc) * F_INTERP;
            }
            out[moff + 2 * probN + n] = r;
        }
    }
}

// ---------------- launch ----------------
extern "C" void kernel_launch(void* const* d_in, const int* in_sizes, int n_in,
                              void* d_out, int out_size) {
    const float* x_i     = (const float*)d_in[0];
    const float* x_e     = (const float*)d_in[1];
    const float* Wsrc_ii = (const float*)d_in[2];
    const float* Wdst_ii = (const float*)d_in[3];
    const float* asrc_ii = (const float*)d_in[4];
    const float* adst_ii = (const float*)d_in[5];
    const float* b_ii    = (const float*)d_in[6];
    // d_in[7..11]: ie branch — unused downstream in the reference; skipped.
    const float* Wsrc_ei = (const float*)d_in[12];
    const float* Wdst_ei = (const float*)d_in[13];
    const float* asrc_ei = (const float*)d_in[14];
    const float* adst_ei = (const float*)d_in[15];
    const float* b_ei    = (const float*)d_in[16];
    const float* linW    = (const float*)d_in[17];
    const float* linb    = (const float*)d_in[18];
    const float* rn      = (const float*)d_in[19];
    const int*   eii     = (const int*)d_in[20];
    const int*   eei     = (const int*)d_in[22];
    const int*   labels  = (const int*)d_in[23];
    const int*   idxtr   = (const int*)d_in[24];
    const int*   chosen  = (const int*)d_in[25];
    float* out = (float*)d_out;

    void *p_deg_ii, *p_deg_ei, *p_tf, *p_iv;
    cudaGetSymbolAddress(&p_deg_ii, g_deg_ii);
    cudaGetSymbolAddress(&p_deg_ei, g_deg_ei);
    cudaGetSymbolAddress(&p_tf, g_trainflag);
    cudaGetSymbolAddress(&p_iv, g_invch);

    cudaMemsetAsync(p_deg_ii, 0, (size_t)N_I * sizeof(int));
    cudaMemsetAsync(p_deg_ei, 0, (size_t)N_I * sizeof(int));
    cudaMemsetAsync(p_tf, 0, (size_t)N_I * sizeof(int));
    cudaMemsetAsync(p_iv, 0xFF, (size_t)N_I * sizeof(int));   // -1

    cudaFuncSetAttribute(k_gemm_all, cudaFuncAttributeMaxDynamicSharedMemorySize, SMEM_BYTES);
    k_gemm_all<<<SCB + TII + TEI, 256, SMEM_BYTES>>>(
        x_i, Wsrc_ii, asrc_ii, Wdst_ii, adst_ii, Wdst_ei, adst_ei,
        x_e, Wsrc_ei, asrc_ei, eii, eei, idxtr, chosen);

    k_aggr<<<(N_I + 7) / 8, 256>>>(b_ii, b_ei);

    k_nn3<<<(N_CHOSEN / 8) * 4, 256>>>();

    int probN = N_I + N_CHOSEN;
    int writeExtras = (out_size >= probN * 5) ? 1 : 0;
    k_final<<<(probN + 7) / 8, 256>>>(linW, linb, rn, labels, chosen, out, probN, writeExtras);
}

// round 8
// speedup vs baseline: 1.5674x; 1.0456x over previous
#include <cuda_runtime.h>
#include <math.h>

#define N_I 60000
#define N_E 30000
#define DI  128
#define DE  64
#define HH  64
#define E_II 960000
#define E_EI 480000
#define N_TRAIN 2048
#define N_CHOSEN 1024
#define F_INTERP 0.35f
#define F_SLOPE  0.2f
#define CAP_II 64
#define CAP_EI 48
#define TII ((N_I + 127) / 128)   // 469
#define TEI ((N_E + 127) / 128)   // 235
#define SCB 128                   // scatter blocks prepended to gemm grid
#define SMEM_FLOATS (64*130 + 64*64 + 64 + 256)   // 12736
#define SMEM_BYTES  (SMEM_FLOATS * 4)             // 50944

// ---------------- scratch (static device globals; no allocation) ----------------
__device__ __align__(16) float g_hs_ii[N_I * HH];
__device__ __align__(16) float g_hs_ei[N_E * HH];
__device__ __align__(16) float g_emb[N_I * HH];
__device__ float g_s_ii[N_I];
__device__ float g_d_ii[N_I];
__device__ float g_d_ei[N_I];
__device__ float g_s_ei[N_E];
__device__ int   g_deg_ii[N_I];
__device__ int   g_deg_ei[N_I];
__device__ int   g_bkt_ii[(size_t)N_I * CAP_II];
__device__ int   g_bkt_ei[(size_t)N_I * CAP_EI];
__device__ __align__(16) float g_ce[N_CHOSEN * HH];
__device__ float g_sq[N_CHOSEN];
__device__ unsigned long long g_nbpack[N_CHOSEN];
__device__ int   g_trainflag[N_I];
__device__ int   g_invch[N_I];

// ---------------- packed f32x2 helpers (Blackwell FFMA2) ----------------
__device__ __forceinline__ unsigned long long pk2(float x) {
    unsigned long long r;
    asm("mov.b64 %0, {%1, %1};" : "=l"(r) : "f"(x));
    return r;
}
__device__ __forceinline__ void fma2(unsigned long long& d, unsigned long long a,
                                     unsigned long long b) {
    asm("fma.rn.f32x2 %0, %1, %2, %0;" : "+l"(d) : "l"(a), "l"(b));
}
__device__ __forceinline__ void upk(unsigned long long v, float& lo, float& hi) {
    asm("mov.b64 {%0, %1}, %2;" : "=f"(lo), "=f"(hi) : "l"(v));
}

// ---------------- GEMM tile (256 threads): HS = A@W, S = HS@asrc, D = A@wd ----------------
__device__ void gemm_tile(const float* __restrict__ A, const float* __restrict__ W,
                          const float* __restrict__ asrc,
                          const float* __restrict__ Wdst0, const float* __restrict__ adst0,
                          const float* __restrict__ Wdst1, const float* __restrict__ adst1,
                          float* __restrict__ HS, float* __restrict__ S,
                          float* __restrict__ D0, float* __restrict__ D1,
                          int M, int K, int row0, float* sm) {
    float* As  = sm;              // [64][130]
    float* Ws  = sm + 64 * 130;   // [64][64]
    float* asc = Ws + 64 * 64;    // [64]
    float* wds = asc + 64;        // [256]

    const int tid  = threadIdx.x;
    const int Mloc = M - row0;
    const int tr = tid >> 3;      // 0..31
    const int tc = tid & 7;       // 0..7

    if (Wdst0 && tid < K) {
        float s0 = 0.f, s1 = 0.f;
#pragma unroll 16
        for (int c = 0; c < HH; c++) {
            s0 += __ldg(&Wdst0[tid * HH + c]) * __ldg(&adst0[c]);
            s1 += __ldg(&Wdst1[tid * HH + c]) * __ldg(&adst1[c]);
        }
        wds[tid]       = s0;
        wds[128 + tid] = s1;
    }
    if (tid < 64) asc[tid] = asrc[tid];

    unsigned long long acc[2][8];
#pragma unroll
    for (int p = 0; p < 2; p++)
#pragma unroll
        for (int j = 0; j < 8; j++) acc[p][j] = 0ull;
    float d0 = 0.f, d1 = 0.f;

    const int nch = K >> 6;
    for (int ch = 0; ch < nch; ch++) {
        const int kk = ch << 6;
        __syncthreads();
        for (int i = tid; i < 128 * 64; i += 256) {
            int r = i >> 6, k = i & 63;
            As[k * 130 + r] = (r < Mloc) ? A[(size_t)(row0 + r) * K + kk + k] : 0.f;
        }
        for (int i = tid; i < 64 * 64; i += 256) Ws[i] = W[kk * 64 + i];
        __syncthreads();

        const float* AsB = As + tr * 4;
        const float* WsB = Ws + tc * 8;
        for (int k = 0; k < 64; k++) {
            unsigned long long a0 = *(const unsigned long long*)(AsB + k * 130);
            unsigned long long a1 = *(const unsigned long long*)(AsB + k * 130 + 2);
            float4 b0 = *(const float4*)(WsB + k * 64);
            float4 b1 = *(const float4*)(WsB + k * 64 + 4);
            unsigned long long bd[8];
            bd[0] = pk2(b0.x); bd[1] = pk2(b0.y); bd[2] = pk2(b0.z); bd[3] = pk2(b0.w);
            bd[4] = pk2(b1.x); bd[5] = pk2(b1.y); bd[6] = pk2(b1.z); bd[7] = pk2(b1.w);
#pragma unroll
            for (int j = 0; j < 8; j++) {
                fma2(acc[0][j], a0, bd[j]);
                fma2(acc[1][j], a1, bd[j]);
            }
        }
        if (Wdst0 && tid < 128 && tid < Mloc) {
            for (int k = 0; k < 64; k++) {
                float a = As[k * 130 + tid];
                d0 += a * wds[kk + k];
                d1 += a * wds[128 + kk + k];
            }
        }
    }

    float ar[8];
#pragma unroll
    for (int j = 0; j < 8; j++) ar[j] = asc[tc * 8 + j];

#pragma unroll
    for (int p = 0; p < 2; p++) {
        float lo[8], hi[8];
#pragma unroll
        for (int j = 0; j < 8; j++) upk(acc[p][j], lo[j], hi[j]);
        int rl = tr * 4 + 2 * p;
        int rh = rl + 1;
        float sl = lo[0]*ar[0]+lo[1]*ar[1]+lo[2]*ar[2]+lo[3]*ar[3]+lo[4]*ar[4]+lo[5]*ar[5]+lo[6]*ar[6]+lo[7]*ar[7];
        float sh = hi[0]*ar[0]+hi[1]*ar[1]+hi[2]*ar[2]+hi[3]*ar[3]+hi[4]*ar[4]+hi[5]*ar[5]+hi[6]*ar[6]+hi[7]*ar[7];
#pragma unroll
        for (int off = 4; off; off >>= 1) {
            sl += __shfl_down_sync(0xffffffffu, sl, off, 8);
            sh += __shfl_down_sync(0xffffffffu, sh, off, 8);
        }
        if (rl < Mloc) {
            float* dl = &HS[(size_t)(row0 + rl) * 64 + tc * 8];
            *(float4*)dl       = make_float4(lo[0], lo[1], lo[2], lo[3]);
            *(float4*)(dl + 4) = make_float4(lo[4], lo[5], lo[6], lo[7]);
            if (tc == 0) S[row0 + rl] = sl;
        }
        if (rh < Mloc) {
            float* dh = &HS[(size_t)(row0 + rh) * 64 + tc * 8];
            *(float4*)dh       = make_float4(hi[0], hi[1], hi[2], hi[3]);
            *(float4*)(dh + 4) = make_float4(hi[4], hi[5], hi[6], hi[7]);
            if (tc == 0) S[row0 + rh] = sh;
        }
    }
    if (Wdst0 && tid < 128 && tid < Mloc) {
        D0[row0 + tid] = d0;
        D1[row0 + tid] = d1;
    }
}

// ---------------- combined launch: scatter blocks [0,SCB) || GEMM blocks [SCB,..) ---------
__global__ void __launch_bounds__(256, 2)
k_gemm_all(const float* __restrict__ x_i, const float* __restrict__ Wsrc_ii,
           const float* __restrict__ asrc_ii,
           const float* __restrict__ Wdst_ii, const float* __restrict__ adst_ii,
           const float* __restrict__ Wdst_ei, const float* __restrict__ adst_ei,
           const float* __restrict__ x_e, const float* __restrict__ Wsrc_ei,
           const float* __restrict__ asrc_ei,
           const int* __restrict__ eii, const int* __restrict__ eei,
           const int* __restrict__ idxtr, const int* __restrict__ chosen) {
    extern __shared__ float sm[];
    const int bid = blockIdx.x;
    if (bid < SCB) {
        const int TOT = E_II + E_EI + N_TRAIN + N_CHOSEN + N_CHOSEN;
        for (int idx = bid * 256 + threadIdx.x; idx < TOT; idx += SCB * 256) {
            if (idx < E_II) {
                int d = eii[E_II + idx];
                int pos = atomicAdd(&g_deg_ii[d], 1);
                if (pos < CAP_II) g_bkt_ii[(size_t)d * CAP_II + pos] = eii[idx];
            } else if (idx < E_II + E_EI) {
                int e2 = idx - E_II;
                int d = eei[E_EI + e2];
                int pos = atomicAdd(&g_deg_ei[d], 1);
                if (pos < CAP_EI) g_bkt_ei[(size_t)d * CAP_EI + pos] = eei[e2];
            } else if (idx < E_II + E_EI + N_TRAIN) {
                g_trainflag[idxtr[idx - E_II - E_EI]] = 1;
            } else if (idx < E_II + E_EI + N_TRAIN + N_CHOSEN) {
                int j = idx - E_II - E_EI - N_TRAIN;
                g_invch[chosen[j]] = j;
            } else {
                g_nbpack[idx - E_II - E_EI - N_TRAIN - N_CHOSEN] = 0xFFFFFFFFFFFFFFFFull;
            }
        }
        return;
    }
    int t = bid - SCB;
    if (t < TII)
        gemm_tile(x_i, Wsrc_ii, asrc_ii, Wdst_ii, adst_ii, Wdst_ei, adst_ei,
                  g_hs_ii, g_s_ii, g_d_ii, g_d_ei, N_I, 128, t * 128, sm);
    else
        gemm_tile(x_e, Wsrc_ei, asrc_ei, nullptr, nullptr, nullptr, nullptr,
                  g_hs_ei, g_s_ei, nullptr, nullptr, N_E, 64, (t - TII) * 128, sm);
}

// ---------------- per-graph gather: 2 edges/step, half-warp float4 rows ----------------
// Lanes 0-15 gather edge 2t's 256B row; lanes 16-31 edge 2t+1's. Returns the
// per-lane normalized partial (halves merged by caller via shfl_xor 16).
__device__ __forceinline__ float4 aggr_one(const int* __restrict__ bkt, int deg,
                                           const float* __restrict__ S, float dval,
                                           const float* __restrict__ HS,
                                           int lane, int half, int qlane) {
    float4 v = make_float4(0.f, 0.f, 0.f, 0.f);
    float esum = 0.f;
    for (int base = 0; base < deg; base += 32) {
        int j = base + lane;
        int sidx = 0;
        float e = 0.f;
        if (j < deg) {
            sidx = bkt[j];
            float a = __ldg(&S[sidx]) + dval;
            a = a > 0.f ? a : F_SLOPE * a;
            e = expf(a);
        }
        int cnt = min(32, deg - base);
        int steps = (cnt + 1) >> 1;
#pragma unroll 8
        for (int t = 0; t < steps; t++) {
            int sl = 2 * t + half;             // out-of-range edges have e=0, sidx=0
            float et = __shfl_sync(0xffffffffu, e, sl);
            int   st = __shfl_sync(0xffffffffu, sidx, sl);
            float4 h = *(const float4*)&HS[(size_t)st * 64 + qlane * 4];
            v.x += et * h.x; v.y += et * h.y; v.z += et * h.z; v.w += et * h.w;
        }
        esum += e;
    }
#pragma unroll
    for (int off = 16; off; off >>= 1)
        esum += __shfl_xor_sync(0xffffffffu, esum, off);
    if (esum > 0.f) {
        float inv = 1.f / esum;
        v.x *= inv; v.y *= inv; v.z *= inv; v.w *= inv;
    }
    return v;
}

// ---------------- fused aggregation + bias + relu -> emb (+ce/sq for chosen) ----------------
__global__ void k_aggr(const float* __restrict__ b_ii, const float* __restrict__ b_ei) {
    int dst = blockIdx.x * (blockDim.x >> 5) + (threadIdx.x >> 5);
    int lane = threadIdx.x & 31;
    int half = lane >> 4, qlane = lane & 15;
    if (dst >= N_I) return;

    float4 v0 = aggr_one(&g_bkt_ii[(size_t)dst * CAP_II], min(g_deg_ii[dst], CAP_II),
                         g_s_ii, g_d_ii[dst], g_hs_ii, lane, half, qlane);
    float4 v1 = aggr_one(&g_bkt_ei[(size_t)dst * CAP_EI], min(g_deg_ei[dst], CAP_EI),
                         g_s_ei, g_d_ei[dst], g_hs_ei, lane, half, qlane);
    float4 v;
    v.x = v0.x + v1.x; v.y = v0.y + v1.y; v.z = v0.z + v1.z; v.w = v0.w + v1.w;
    // merge the two half-warp partials (lane q and lane q+16 hold the same cols)
    v.x += __shfl_xor_sync(0xffffffffu, v.x, 16);
    v.y += __shfl_xor_sync(0xffffffffu, v.y, 16);
    v.z += __shfl_xor_sync(0xffffffffu, v.z, 16);
    v.w += __shfl_xor_sync(0xffffffffu, v.w, 16);

    float4 bi = *(const float4*)&b_ii[qlane * 4];
    float4 be = *(const float4*)&b_ei[qlane * 4];
    float4 o;
    o.x = 0.5f * (v.x + bi.x + be.x); o.x = o.x > 0.f ? o.x : 0.f;
    o.y = 0.5f * (v.y + bi.y + be.y); o.y = o.y > 0.f ? o.y : 0.f;
    o.z = 0.5f * (v.z + bi.z + be.z); o.z = o.z > 0.f ? o.z : 0.f;
    o.w = 0.5f * (v.w + bi.w + be.w); o.w = o.w > 0.f ? o.w : 0.f;

    if (half == 0)
        *(float4*)&g_emb[(size_t)dst * 64 + qlane * 4] = o;

    int ic = g_invch[dst];
    if (ic >= 0) {
        if (half == 0)
            *(float4*)&g_ce[(size_t)ic * 64 + qlane * 4] = o;
        float sq = o.x * o.x + o.y * o.y + o.z * o.z + o.w * o.w;
#pragma unroll
        for (int off = 8; off; off >>= 1)
            sq += __shfl_xor_sync(0xffffffffu, sq, off);
        if (lane == 0) g_sq[ic] = sq;
    }
}

// ---------------- NN: block = 8 i's x 256-j chunk; packed atomicMin merge ----------------
__global__ void k_nn3() {
    __shared__ float tile[64 * 65];
    __shared__ float sqj[64];
    __shared__ float cei[8 * 64];
    int tid = threadIdx.x;
    int wid = tid >> 5, lane = tid & 31;
    int i = (blockIdx.x >> 2) * 8 + wid;
    int jbase = (blockIdx.x & 3) * 256;

    cei[wid * 64 + lane]      = g_ce[i * 64 + lane];
    cei[wid * 64 + 32 + lane] = g_ce[i * 64 + 32 + lane];
    const float sqi = g_sq[i];
    float best = 3.4e38f;
    int bestj = 0x7fffffff;

    for (int tb = jbase; tb < jbase + 256; tb += 64) {
        __syncthreads();
        for (int idx = tid; idx < 64 * 64; idx += 256) {
            int j = idx >> 6, k = idx & 63;
            tile[j * 65 + k] = g_ce[(tb + j) * 64 + k];
        }
        if (tid < 64) sqj[tid] = g_sq[tb + tid];
        __syncthreads();

#pragma unroll
        for (int half = 0; half < 2; half++) {
            int jl = lane + half * 32;
            int j = tb + jl;
            if (j == i) continue;
            float dot = 0.f;
#pragma unroll 16
            for (int k = 0; k < 64; k++) dot += cei[wid * 64 + k] * tile[jl * 65 + k];
            float d2 = sqi + sqj[jl] - 2.f * dot;
            d2 = d2 > 0.f ? d2 : 0.f;
            if (d2 < best || (d2 == best && j < bestj)) { best = d2; bestj = j; }
        }
    }
#pragma unroll
    for (int off = 16; off; off >>= 1) {
        float ob = __shfl_down_sync(0xffffffffu, best, off);
        int   oj = __shfl_down_sync(0xffffffffu, bestj, off);
        if (ob < best || (ob == best && oj < bestj)) { best = ob; bestj = oj; }
    }
    if (lane == 0) {
        unsigned long long pk = ((unsigned long long)__float_as_uint(best) << 32) |
                                (unsigned)bestj;
        atomicMin(&g_nbpack[i], pk);
    }
}

// ---------------- classifier head + softmax + extras ----------------
__global__ void k_final(const float* __restrict__ linW, const float* __restrict__ linb,
                        const float* __restrict__ rn, const int* __restrict__ labels,
                        const int* __restrict__ chosen,
                        float* __restrict__ out, int probN, int writeExtras) {
    int n = blockIdx.x * (blockDim.x >> 5) + (threadIdx.x >> 5);
    int lane = threadIdx.x & 31;
    if (n >= probN) return;
    float v0, v1;
    if (n < N_I) {
        v0 = g_emb[n * 64 + lane];
        v1 = g_emb[n * 64 + 32 + lane];
    } else {
        int i = n - N_I;
        int nbi = (int)(g_nbpack[i] & 0xFFFFFFFFull);
        float c0 = g_ce[i * 64 + lane],   c1 = g_ce[i * 64 + 32 + lane];
        float n0 = g_ce[nbi * 64 + lane], n1 = g_ce[nbi * 64 + 32 + lane];
        v0 = c0 + (n0 - c0) * F_INTERP;
        v1 = c1 + (n1 - c1) * F_INTERP;
    }
    float l0 = v0 * __ldg(&linW[lane * 2])     + v1 * __ldg(&linW[(lane + 32) * 2]);
    float l1 = v0 * __ldg(&linW[lane * 2 + 1]) + v1 * __ldg(&linW[(lane + 32) * 2 + 1]);
#pragma unroll
    for (int off = 16; off; off >>= 1) {
        l0 += __shfl_down_sync(0xffffffffu, l0, off);
        l1 += __shfl_down_sync(0xffffffffu, l1, off);
    }
    if (lane == 0) {
        l0 += __ldg(&linb[0]);
        l1 += __ldg(&linb[1]);
        float m = fmaxf(l0, l1);
        float e0 = expf(l0 - m), e1 = expf(l1 - m);
        float inv = 1.f / (e0 + e1);
        out[n * 2]     = e0 * inv;
        out[n * 2 + 1] = e1 * inv;
        if (writeExtras) {
            int moff = probN * 2;
            out[moff + n]         = (n >= N_I) ? 1.f : (g_trainflag[n] ? 1.f : 0.f);
            out[moff + probN + n] = (n < N_I) ? (float)labels[n] : 1.f;
            float r;
            if (n < N_I) r = rn[n];
            else {
                int i = n - N_I;
                int nbi = (int)(g_nbpack[i] & 0xFFFFFFFFull);
                float rc = rn[chosen[i]];
                r = rc + (rn[chosen[nbi]] - rc) * F_INTERP;
            }
            out[moff + 2 * probN + n] = r;
        }
    }
}

// ---------------- launch ----------------
extern "C" void kernel_launch(void* const* d_in, const int* in_sizes, int n_in,
                              void* d_out, int out_size) {
    const float* x_i     = (const float*)d_in[0];
    const float* x_e     = (const float*)d_in[1];
    const float* Wsrc_ii = (const float*)d_in[2];
    const float* Wdst_ii = (const float*)d_in[3];
    const float* asrc_ii = (const float*)d_in[4];
    const float* adst_ii = (const float*)d_in[5];
    const float* b_ii    = (const float*)d_in[6];
    // d_in[7..11]: ie branch — unused downstream in the reference; skipped.
    const float* Wsrc_ei = (const float*)d_in[12];
    const float* Wdst_ei = (const float*)d_in[13];
    const float* asrc_ei = (const float*)d_in[14];
    const float* adst_ei = (const float*)d_in[15];
    const float* b_ei    = (const float*)d_in[16];
    const float* linW    = (const float*)d_in[17];
    const float* linb    = (const float*)d_in[18];
    const float* rn      = (const float*)d_in[19];
    const int*   eii     = (const int*)d_in[20];
    const int*   eei     = (const int*)d_in[22];
    const int*   labels  = (const int*)d_in[23];
    const int*   idxtr   = (const int*)d_in[24];
    const int*   chosen  = (const int*)d_in[25];
    float* out = (float*)d_out;

    void *p_deg_ii, *p_deg_ei, *p_tf, *p_iv;
    cudaGetSymbolAddress(&p_deg_ii, g_deg_ii);
    cudaGetSymbolAddress(&p_deg_ei, g_deg_ei);
    cudaGetSymbolAddress(&p_tf, g_trainflag);
    cudaGetSymbolAddress(&p_iv, g_invch);

    cudaMemsetAsync(p_deg_ii, 0, (size_t)N_I * sizeof(int));
    cudaMemsetAsync(p_deg_ei, 0, (size_t)N_I * sizeof(int));
    cudaMemsetAsync(p_tf, 0, (size_t)N_I * sizeof(int));
    cudaMemsetAsync(p_iv, 0xFF, (size_t)N_I * sizeof(int));   // -1

    cudaFuncSetAttribute(k_gemm_all, cudaFuncAttributeMaxDynamicSharedMemorySize, SMEM_BYTES);
    k_gemm_all<<<SCB + TII + TEI, 256, SMEM_BYTES>>>(
        x_i, Wsrc_ii, asrc_ii, Wdst_ii, adst_ii, Wdst_ei, adst_ei,
        x_e, Wsrc_ei, asrc_ei, eii, eei, idxtr, chosen);

    k_aggr<<<(N_I + 7) / 8, 256>>>(b_ii, b_ei);

    k_nn3<<<(N_CHOSEN / 8) * 4, 256>>>();

    int probN = N_I + N_CHOSEN;
    int writeExtras = (out_size >= probN * 5) ? 1 : 0;
    k_final<<<(probN + 7) / 8, 256>>>(linW, linb, rn, labels, chosen, out, probN, writeExtras);
}

// round 9
// speedup vs baseline: 1.6416x; 1.0473x over previous
#include <cuda_runtime.h>
#include <math.h>

#define N_I 60000
#define N_E 30000
#define DI  128
#define DE  64
#define HH  64
#define E_II 960000
#define E_EI 480000
#define N_TRAIN 2048
#define N_CHOSEN 1024
#define F_INTERP 0.35f
#define F_SLOPE  0.2f
#define CAP_II 64
#define CAP_EI 48
#define TII ((N_I + 127) / 128)   // 469
#define TEI ((N_E + 127) / 128)   // 235
#define SCB 128                   // scatter blocks prepended to gemm grid
#define NNB ((N_CHOSEN / 8) * 4)  // 512 nn blocks prepended to final grid
#define FRB ((N_I + 7) / 8)       // 7500 final-real blocks
#define SMEM_FLOATS (64*130 + 64*64 + 64 + 256)   // 12736
#define SMEM_BYTES  (SMEM_FLOATS * 4)             // 50944

// ---------------- scratch (static device globals; zero-initialized at load) ----------------
// Self-cleaning invariant: every kernel_launch call leaves deg/trainflag/invch zeroed
// (done by k_nnfinal after last use), so capture and each replay see identical state.
__device__ __align__(16) float g_hs_ii[N_I * HH];
__device__ __align__(16) float g_hs_ei[N_E * HH];
__device__ __align__(16) float g_emb[N_I * HH];
__device__ float g_s_ii[N_I];
__device__ float g_d_ii[N_I];
__device__ float g_d_ei[N_I];
__device__ float g_s_ei[N_E];
__device__ int   g_deg_ii[N_I];
__device__ int   g_deg_ei[N_I];
__device__ int   g_bkt_ii[(size_t)N_I * CAP_II];
__device__ int   g_bkt_ei[(size_t)N_I * CAP_EI];
__device__ __align__(16) float g_ce[N_CHOSEN * HH];
__device__ float g_sq[N_CHOSEN];
__device__ unsigned long long g_nbpack[N_CHOSEN];   // re-armed in k_aggr each call
__device__ int   g_trainflag[N_I];
__device__ int   g_invch[N_I];                       // j+1 encoding; 0 = not chosen

// ---------------- packed f32x2 helpers (Blackwell FFMA2) ----------------
__device__ __forceinline__ unsigned long long pk2(float x) {
    unsigned long long r;
    asm("mov.b64 %0, {%1, %1};" : "=l"(r) : "f"(x));
    return r;
}
__device__ __forceinline__ void fma2(unsigned long long& d, unsigned long long a,
                                     unsigned long long b) {
    asm("fma.rn.f32x2 %0, %1, %2, %0;" : "+l"(d) : "l"(a), "l"(b));
}
__device__ __forceinline__ void upk(unsigned long long v, float& lo, float& hi) {
    asm("mov.b64 {%0, %1}, %2;" : "=f"(lo), "=f"(hi) : "l"(v));
}

// ---------------- GEMM tile (256 threads): HS = A@W, S = HS@asrc, D = A@wd ----------------
__device__ void gemm_tile(const float* __restrict__ A, const float* __restrict__ W,
                          const float* __restrict__ asrc,
                          const float* __restrict__ Wdst0, const float* __restrict__ adst0,
                          const float* __restrict__ Wdst1, const float* __restrict__ adst1,
                          float* __restrict__ HS, float* __restrict__ S,
                          float* __restrict__ D0, float* __restrict__ D1,
                          int M, int K, int row0, float* sm) {
    float* As  = sm;              // [64][130]
    float* Ws  = sm + 64 * 130;   // [64][64]
    float* asc = Ws + 64 * 64;    // [64]
    float* wds = asc + 64;        // [256]

    const int tid  = threadIdx.x;
    const int Mloc = M - row0;
    const int tr = tid >> 3;      // 0..31
    const int tc = tid & 7;       // 0..7

    if (Wdst0 && tid < K) {
        float s0 = 0.f, s1 = 0.f;
#pragma unroll 16
        for (int c = 0; c < HH; c++) {
            s0 += __ldg(&Wdst0[tid * HH + c]) * __ldg(&adst0[c]);
            s1 += __ldg(&Wdst1[tid * HH + c]) * __ldg(&adst1[c]);
        }
        wds[tid]       = s0;
        wds[128 + tid] = s1;
    }
    if (tid < 64) asc[tid] = asrc[tid];

    unsigned long long acc[2][8];
#pragma unroll
    for (int p = 0; p < 2; p++)
#pragma unroll
        for (int j = 0; j < 8; j++) acc[p][j] = 0ull;
    float d0 = 0.f, d1 = 0.f;

    const int nch = K >> 6;
    for (int ch = 0; ch < nch; ch++) {
        const int kk = ch << 6;
        __syncthreads();
        for (int i = tid; i < 128 * 64; i += 256) {
            int r = i >> 6, k = i & 63;
            As[k * 130 + r] = (r < Mloc) ? A[(size_t)(row0 + r) * K + kk + k] : 0.f;
        }
        for (int i = tid; i < 64 * 64; i += 256) Ws[i] = W[kk * 64 + i];
        __syncthreads();

        const float* AsB = As + tr * 4;
        const float* WsB = Ws + tc * 8;
        for (int k = 0; k < 64; k++) {
            unsigned long long a0 = *(const unsigned long long*)(AsB + k * 130);
            unsigned long long a1 = *(const unsigned long long*)(AsB + k * 130 + 2);
            float4 b0 = *(const float4*)(WsB + k * 64);
            float4 b1 = *(const float4*)(WsB + k * 64 + 4);
            unsigned long long bd[8];
            bd[0] = pk2(b0.x); bd[1] = pk2(b0.y); bd[2] = pk2(b0.z); bd[3] = pk2(b0.w);
            bd[4] = pk2(b1.x); bd[5] = pk2(b1.y); bd[6] = pk2(b1.z); bd[7] = pk2(b1.w);
#pragma unroll
            for (int j = 0; j < 8; j++) {
                fma2(acc[0][j], a0, bd[j]);
                fma2(acc[1][j], a1, bd[j]);
            }
        }
        if (Wdst0 && tid < 128 && tid < Mloc) {
            for (int k = 0; k < 64; k++) {
                float a = As[k * 130 + tid];
                d0 += a * wds[kk + k];
                d1 += a * wds[128 + kk + k];
            }
        }
    }

    float ar[8];
#pragma unroll
    for (int j = 0; j < 8; j++) ar[j] = asc[tc * 8 + j];

#pragma unroll
    for (int p = 0; p < 2; p++) {
        float lo[8], hi[8];
#pragma unroll
        for (int j = 0; j < 8; j++) upk(acc[p][j], lo[j], hi[j]);
        int rl = tr * 4 + 2 * p;
        int rh = rl + 1;
        float sl = lo[0]*ar[0]+lo[1]*ar[1]+lo[2]*ar[2]+lo[3]*ar[3]+lo[4]*ar[4]+lo[5]*ar[5]+lo[6]*ar[6]+lo[7]*ar[7];
        float sh = hi[0]*ar[0]+hi[1]*ar[1]+hi[2]*ar[2]+hi[3]*ar[3]+hi[4]*ar[4]+hi[5]*ar[5]+hi[6]*ar[6]+hi[7]*ar[7];
#pragma unroll
        for (int off = 4; off; off >>= 1) {
            sl += __shfl_down_sync(0xffffffffu, sl, off, 8);
            sh += __shfl_down_sync(0xffffffffu, sh, off, 8);
        }
        if (rl < Mloc) {
            float* dl = &HS[(size_t)(row0 + rl) * 64 + tc * 8];
            *(float4*)dl       = make_float4(lo[0], lo[1], lo[2], lo[3]);
            *(float4*)(dl + 4) = make_float4(lo[4], lo[5], lo[6], lo[7]);
            if (tc == 0) S[row0 + rl] = sl;
        }
        if (rh < Mloc) {
            float* dh = &HS[(size_t)(row0 + rh) * 64 + tc * 8];
            *(float4*)dh       = make_float4(hi[0], hi[1], hi[2], hi[3]);
            *(float4*)(dh + 4) = make_float4(hi[4], hi[5], hi[6], hi[7]);
            if (tc == 0) S[row0 + rh] = sh;
        }
    }
    if (Wdst0 && tid < 128 && tid < Mloc) {
        D0[row0 + tid] = d0;
        D1[row0 + tid] = d1;
    }
}

// ---------------- combined launch: scatter blocks [0,SCB) || GEMM blocks [SCB,..) ---------
__global__ void __launch_bounds__(256, 2)
k_gemm_all(const float* __restrict__ x_i, const float* __restrict__ Wsrc_ii,
           const float* __restrict__ asrc_ii,
           const float* __restrict__ Wdst_ii, const float* __restrict__ adst_ii,
           const float* __restrict__ Wdst_ei, const float* __restrict__ adst_ei,
           const float* __restrict__ x_e, const float* __restrict__ Wsrc_ei,
           const float* __restrict__ asrc_ei,
           const int* __restrict__ eii, const int* __restrict__ eei,
           const int* __restrict__ idxtr, const int* __restrict__ chosen) {
    extern __shared__ float sm[];
    const int bid = blockIdx.x;
    if (bid < SCB) {
        const int TOT = E_II + E_EI + N_TRAIN + N_CHOSEN;
        for (int idx = bid * 256 + threadIdx.x; idx < TOT; idx += SCB * 256) {
            if (idx < E_II) {
                int d = eii[E_II + idx];
                int pos = atomicAdd(&g_deg_ii[d], 1);
                if (pos < CAP_II) g_bkt_ii[(size_t)d * CAP_II + pos] = eii[idx];
            } else if (idx < E_II + E_EI) {
                int e2 = idx - E_II;
                int d = eei[E_EI + e2];
                int pos = atomicAdd(&g_deg_ei[d], 1);
                if (pos < CAP_EI) g_bkt_ei[(size_t)d * CAP_EI + pos] = eei[e2];
            } else if (idx < E_II + E_EI + N_TRAIN) {
                g_trainflag[idxtr[idx - E_II - E_EI]] = 1;
            } else {
                int j = idx - E_II - E_EI - N_TRAIN;
                g_invch[chosen[j]] = j + 1;       // 0 = not chosen
            }
        }
        return;
    }
    int t = bid - SCB;
    if (t < TII)
        gemm_tile(x_i, Wsrc_ii, asrc_ii, Wdst_ii, adst_ii, Wdst_ei, adst_ei,
                  g_hs_ii, g_s_ii, g_d_ii, g_d_ei, N_I, 128, t * 128, sm);
    else
        gemm_tile(x_e, Wsrc_ei, asrc_ei, nullptr, nullptr, nullptr, nullptr,
                  g_hs_ei, g_s_ei, nullptr, nullptr, N_E, 64, (t - TII) * 128, sm);
}

// ---------------- per-graph gather: 2 edges/step, half-warp float4 rows ----------------
__device__ __forceinline__ float4 aggr_one(const int* __restrict__ bkt, int deg,
                                           const float* __restrict__ S, float dval,
                                           const float* __restrict__ HS,
                                           int lane, int half, int qlane) {
    float4 v = make_float4(0.f, 0.f, 0.f, 0.f);
    float esum = 0.f;
    for (int base = 0; base < deg; base += 32) {
        int j = base + lane;
        int sidx = 0;
        float e = 0.f;
        if (j < deg) {
            sidx = bkt[j];
            float a = __ldg(&S[sidx]) + dval;
            a = a > 0.f ? a : F_SLOPE * a;
            e = expf(a);
        }
        int cnt = min(32, deg - base);
        int steps = (cnt + 1) >> 1;
#pragma unroll 8
        for (int t = 0; t < steps; t++) {
            int sl = 2 * t + half;             // out-of-range edges have e=0, sidx=0
            float et = __shfl_sync(0xffffffffu, e, sl);
            int   st = __shfl_sync(0xffffffffu, sidx, sl);
            float4 h = *(const float4*)&HS[(size_t)st * 64 + qlane * 4];
            v.x += et * h.x; v.y += et * h.y; v.z += et * h.z; v.w += et * h.w;
        }
        esum += e;
    }
#pragma unroll
    for (int off = 16; off; off >>= 1)
        esum += __shfl_xor_sync(0xffffffffu, esum, off);
    if (esum > 0.f) {
        float inv = 1.f / esum;
        v.x *= inv; v.y *= inv; v.z *= inv; v.w *= inv;
    }
    return v;
}

// ---------------- fused aggregation + bias + relu -> emb (+ce/sq; re-arm nbpack) ---------
__global__ void k_aggr(const float* __restrict__ b_ii, const float* __restrict__ b_ei) {
    int gtid = blockIdx.x * blockDim.x + threadIdx.x;
    if (gtid < N_CHOSEN) g_nbpack[gtid] = 0xFFFFFFFFFFFFFFFFull;  // before k_nn3 runs

    int dst = blockIdx.x * (blockDim.x >> 5) + (threadIdx.x >> 5);
    int lane = threadIdx.x & 31;
    int half = lane >> 4, qlane = lane & 15;
    if (dst >= N_I) return;

    float4 v0 = aggr_one(&g_bkt_ii[(size_t)dst * CAP_II], min(g_deg_ii[dst], CAP_II),
                         g_s_ii, g_d_ii[dst], g_hs_ii, lane, half, qlane);
    float4 v1 = aggr_one(&g_bkt_ei[(size_t)dst * CAP_EI], min(g_deg_ei[dst], CAP_EI),
                         g_s_ei, g_d_ei[dst], g_hs_ei, lane, half, qlane);
    float4 v;
    v.x = v0.x + v1.x; v.y = v0.y + v1.y; v.z = v0.z + v1.z; v.w = v0.w + v1.w;
    v.x += __shfl_xor_sync(0xffffffffu, v.x, 16);
    v.y += __shfl_xor_sync(0xffffffffu, v.y, 16);
    v.z += __shfl_xor_sync(0xffffffffu, v.z, 16);
    v.w += __shfl_xor_sync(0xffffffffu, v.w, 16);

    float4 bi = *(const float4*)&b_ii[qlane * 4];
    float4 be = *(const float4*)&b_ei[qlane * 4];
    float4 o;
    o.x = 0.5f * (v.x + bi.x + be.x); o.x = o.x > 0.f ? o.x : 0.f;
    o.y = 0.5f * (v.y + bi.y + be.y); o.y = o.y > 0.f ? o.y : 0.f;
    o.z = 0.5f * (v.z + bi.z + be.z); o.z = o.z > 0.f ? o.z : 0.f;
    o.w = 0.5f * (v.w + bi.w + be.w); o.w = o.w > 0.f ? o.w : 0.f;

    if (half == 0)
        *(float4*)&g_emb[(size_t)dst * 64 + qlane * 4] = o;

    int ic = g_invch[dst];
    if (ic > 0) {
        ic -= 1;
        if (half == 0)
            *(float4*)&g_ce[(size_t)ic * 64 + qlane * 4] = o;
        float sq = o.x * o.x + o.y * o.y + o.z * o.z + o.w * o.w;
#pragma unroll
        for (int off = 8; off; off >>= 1)
            sq += __shfl_xor_sync(0xffffffffu, sq, off);
        if (lane == 0) g_sq[ic] = sq;
    }
}

// ---------------- merged: NN blocks [0,NNB) || final-real blocks [NNB,NNB+FRB) ------------
__global__ void k_nnfinal(const float* __restrict__ linW, const float* __restrict__ linb,
                          const float* __restrict__ rn, const int* __restrict__ labels,
                          float* __restrict__ out, int probN, int writeExtras) {
    __shared__ float tile[64 * 65];
    __shared__ float sqj[64];
    __shared__ float cei[8 * 64];
    const int tid = threadIdx.x;
    const int wid = tid >> 5, lane = tid & 31;

    if (blockIdx.x < NNB) {
        // ---- NN: 8 i's x 256-j chunk; packed atomicMin merge ----
        int i = (blockIdx.x >> 2) * 8 + wid;
        int jbase = (blockIdx.x & 3) * 256;

        cei[wid * 64 + lane]      = g_ce[i * 64 + lane];
        cei[wid * 64 + 32 + lane] = g_ce[i * 64 + 32 + lane];
        const float sqi = g_sq[i];
        float best = 3.4e38f;
        int bestj = 0x7fffffff;

        for (int tb = jbase; tb < jbase + 256; tb += 64) {
            __syncthreads();
            for (int idx = tid; idx < 64 * 64; idx += 256) {
                int j = idx >> 6, k = idx & 63;
                tile[j * 65 + k] = g_ce[(tb + j) * 64 + k];
            }
            if (tid < 64) sqj[tid] = g_sq[tb + tid];
            __syncthreads();

#pragma unroll
            for (int hh = 0; hh < 2; hh++) {
                int jl = lane + hh * 32;
                int j = tb + jl;
                if (j == i) continue;
                float dot = 0.f;
#pragma unroll 16
                for (int k = 0; k < 64; k++) dot += cei[wid * 64 + k] * tile[jl * 65 + k];
                float d2 = sqi + sqj[jl] - 2.f * dot;
                d2 = d2 > 0.f ? d2 : 0.f;
                if (d2 < best || (d2 == best && j < bestj)) { best = d2; bestj = j; }
            }
        }
#pragma unroll
        for (int off = 16; off; off >>= 1) {
            float ob = __shfl_down_sync(0xffffffffu, best, off);
            int   oj = __shfl_down_sync(0xffffffffu, bestj, off);
            if (ob < best || (ob == best && oj < bestj)) { best = ob; bestj = oj; }
        }
        if (lane == 0) {
            unsigned long long pk = ((unsigned long long)__float_as_uint(best) << 32) |
                                    (unsigned)bestj;
            atomicMin(&g_nbpack[i], pk);
        }
        return;
    }

    // ---- final for real nodes n < N_I (+ self-clean state for next replay) ----
    int n = (blockIdx.x - NNB) * 8 + wid;
    if (n >= N_I) return;
    float v0 = g_emb[n * 64 + lane];
    float v1 = g_emb[n * 64 + 32 + lane];
    float l0 = v0 * __ldg(&linW[lane * 2])     + v1 * __ldg(&linW[(lane + 32) * 2]);
    float l1 = v0 * __ldg(&linW[lane * 2 + 1]) + v1 * __ldg(&linW[(lane + 32) * 2 + 1]);
#pragma unroll
    for (int off = 16; off; off >>= 1) {
        l0 += __shfl_down_sync(0xffffffffu, l0, off);
        l1 += __shfl_down_sync(0xffffffffu, l1, off);
    }
    if (lane == 0) {
        l0 += __ldg(&linb[0]);
        l1 += __ldg(&linb[1]);
        float m = fmaxf(l0, l1);
        float e0 = expf(l0 - m), e1 = expf(l1 - m);
        float inv = 1.f / (e0 + e1);
        out[n * 2]     = e0 * inv;
        out[n * 2 + 1] = e1 * inv;
        if (writeExtras) {
            int moff = probN * 2;
            out[moff + n]             = g_trainflag[n] ? 1.f : 0.f;
            out[moff + probN + n]     = (float)labels[n];
            out[moff + 2 * probN + n] = rn[n];
        }
    }
    // self-clean (after all uses of this node's entries)
    if (lane == 0)      g_trainflag[n] = 0;
    else if (lane == 1) g_invch[n] = 0;
    else if (lane == 2) g_deg_ii[n] = 0;
    else if (lane == 3) g_deg_ei[n] = 0;
}

// ---------------- synthetic SMOTE rows: probs + extras ----------------
__global__ void k_synth(const float* __restrict__ linW, const float* __restrict__ linb,
                        const float* __restrict__ rn, const int* __restrict__ chosen,
                        float* __restrict__ out, int probN, int writeExtras) {
    int i = blockIdx.x * (blockDim.x >> 5) + (threadIdx.x >> 5);
    int lane = threadIdx.x & 31;
    if (i >= N_CHOSEN) return;
    int nbi = (int)(g_nbpack[i] & 0xFFFFFFFFull);
    float c0 = g_ce[i * 64 + lane],   c1 = g_ce[i * 64 + 32 + lane];
    float n0 = g_ce[nbi * 64 + lane], n1 = g_ce[nbi * 64 + 32 + lane];
    float v0 = c0 + (n0 - c0) * F_INTERP;
    float v1 = c1 + (n1 - c1) * F_INTERP;
    float l0 = v0 * __ldg(&linW[lane * 2])     + v1 * __ldg(&linW[(lane + 32) * 2]);
    float l1 = v0 * __ldg(&linW[lane * 2 + 1]) + v1 * __ldg(&linW[(lane + 32) * 2 + 1]);
#pragma unroll
    for (int off = 16; off; off >>= 1) {
        l0 += __shfl_down_sync(0xffffffffu, l0, off);
        l1 += __shfl_down_sync(0xffffffffu, l1, off);
    }
    if (lane == 0) {
        int n = N_I + i;
        l0 += __ldg(&linb[0]);
        l1 += __ldg(&linb[1]);
        float m = fmaxf(l0, l1);
        float e0 = expf(l0 - m), e1 = expf(l1 - m);
        float inv = 1.f / (e0 + e1);
        out[n * 2]     = e0 * inv;
        out[n * 2 + 1] = e1 * inv;
        if (writeExtras) {
            int moff = probN * 2;
            out[moff + n]             = 1.f;
            out[moff + probN + n]     = 1.f;
            float rc = rn[chosen[i]];
            out[moff + 2 * probN + n] = rc + (rn[chosen[nbi]] - rc) * F_INTERP;
        }
    }
}

// ---------------- launch ----------------
extern "C" void kernel_launch(void* const* d_in, const int* in_sizes, int n_in,
                              void* d_out, int out_size) {
    const float* x_i     = (const float*)d_in[0];
    const float* x_e     = (const float*)d_in[1];
    const float* Wsrc_ii = (const float*)d_in[2];
    const float* Wdst_ii = (const float*)d_in[3];
    const float* asrc_ii = (const float*)d_in[4];
    const float* adst_ii = (const float*)d_in[5];
    const float* b_ii    = (const float*)d_in[6];
    // d_in[7..11]: ie branch — unused downstream in the reference; skipped.
    const float* Wsrc_ei = (const float*)d_in[12];
    const float* Wdst_ei = (const float*)d_in[13];
    const float* asrc_ei = (const float*)d_in[14];
    const float* adst_ei = (const float*)d_in[15];
    const float* b_ei    = (const float*)d_in[16];
    const float* linW    = (const float*)d_in[17];
    const float* linb    = (const float*)d_in[18];
    const float* rn      = (const float*)d_in[19];
    const int*   eii     = (const int*)d_in[20];
    const int*   eei     = (const int*)d_in[22];
    const int*   labels  = (const int*)d_in[23];
    const int*   idxtr   = (const int*)d_in[24];
    const int*   chosen  = (const int*)d_in[25];
    float* out = (float*)d_out;

    cudaFuncSetAttribute(k_gemm_all, cudaFuncAttributeMaxDynamicSharedMemorySize, SMEM_BYTES);
    k_gemm_all<<<SCB + TII + TEI, 256, SMEM_BYTES>>>(
        x_i, Wsrc_ii, asrc_ii, Wdst_ii, adst_ii, Wdst_ei, adst_ei,
        x_e, Wsrc_ei, asrc_ei, eii, eei, idxtr, chosen);

    k_aggr<<<(N_I + 7) / 8, 256>>>(b_ii, b_ei);

    int probN = N_I + N_CHOSEN;
    int writeExtras = (out_size >= probN * 5) ? 1 : 0;
    k_nnfinal<<<NNB + FRB, 256>>>(linW, linb, rn, labels, out, probN, writeExtras);
    k_synth<<<(N_CHOSEN + 7) / 8, 256>>>(linW, linb, rn, chosen, out, probN, writeExtras);
}